// round 15
// baseline (speedup 1.0000x reference)
#include <cuda_runtime.h>
#include <cuda_bf16.h>
#include <cstdint>

// CGBlock: per-slice 3-layer MLP (Linear->BN->ReLU x2 ->Linear), context gate,
// max-pool. B=256, S=512, D=128 fp32.
// cta_group::2 bf16x3-split MMA, M=256 per 2-CTA cluster, 2 CTAs/SM.
// R11: TS-mode MMA (A lives in TMEM as bf16x2; D=128 + Ahi=64 + Alo=64 cols).
// Normalize writes A' via STTM (256B/cyc) instead of swizzled smem stores;
// MMA reads only W from SMEM. Staging: coalesced raw smem -> STTM.

#define THREADS 512

#if defined(__CUDA_ARCH__) && (defined(__CUDA_ARCH_FEAT_SM103_ALL) || defined(__CUDA_ARCH_FEAT_SM100_ALL) || defined(__CUDA_ARCH_FEAT_SM101_ALL))
#define USE_TC 1
#else
#define USE_TC 0
#endif

// ---------------- shared device state ----------------
__device__ float4 g_c_out[256 * 32];
__device__ int g_flag = 0;
__device__ float4 g_part[1024 * 32];

// ---------------- TC-path SMEM layout (bytes) ----------------
#define OFF_TMEM 0
#define OFF_MBAR 8
#define OFF_RAW  1024      // raw fp32 staging: 128 rows x 132 floats = 67584
#define OFF_WHI  68608     // W_hi half: 64r x 128k bf16 blocked-SW128 = 16384
#define OFF_WLO  84992     // W_lo half: 16384
#define OFF_SC   101376    // BN scale f32[128]
#define OFF_SH   101888    // BN shift f32[128]
#define OFF_PST  102400    // f32[1024]: 512 sum + 512 sumsq partials
#define SM_TC_BYTES 106496

// TMEM columns
#define TM_D   0           // D: 128 cols fp32
#define TM_AH  128         // A_hi: 64 cols bf16x2
#define TM_AL  192         // A_lo: 64 cols bf16x2
#define TMEM_COLS 256

// idesc kind::f16 cg2: c=F32, a=BF16, b=BF16, N=128, M=256
#define IDESC2 0x10200490u

typedef unsigned long long u64;

__device__ __forceinline__ uint32_t smem_u32(const void* p) {
    uint32_t a;
    asm("{ .reg .u64 t; cvta.to.shared.u64 t, %1; cvt.u32.u64 %0, t; }" : "=r"(a) : "l"(p));
    return a;
}

// Blocked SW128 addr, 64-row bf16 tile (8 atom-rows x 2 atom-cols).
__device__ __forceinline__ uint32_t swb64(int rl, int j0) {
    uint32_t off = (uint32_t)((((rl >> 3) + ((j0 >> 6) << 3)) << 10) + ((rl & 7) << 7) + ((j0 & 63) << 1));
    return off ^ ((off >> 3) & 0x70);
}

// Split one fp32 pair into bf16x2 hi (truncate) + bf16x2 lo (residual, rn).
__device__ __forceinline__ void split_pair(float x, float y, uint32_t& h, uint32_t& l) {
    uint32_t bx = __float_as_uint(x), by = __float_as_uint(y);
    asm("prmt.b32 %0, %1, %2, 0x7632;" : "=r"(h) : "r"(bx), "r"(by));
    float lx = x - __uint_as_float(bx & 0xFFFF0000u);
    float ly = y - __uint_as_float(by & 0xFFFF0000u);
    asm("cvt.rn.bf16x2.f32 %0, %1, %2;" : "=r"(l) : "f"(ly), "f"(lx));
}
// 8-float variant for weight splitting into smem tiles.
__device__ __forceinline__ void split8f(const float* f, uint4& h, uint4& l) {
    uint32_t hh[4], ll[4];
#pragma unroll
    for (int i = 0; i < 4; ++i) split_pair(f[2 * i], f[2 * i + 1], hh[i], ll[i]);
    h = make_uint4(hh[0], hh[1], hh[2], hh[3]);
    l = make_uint4(ll[0], ll[1], ll[2], ll[3]);
}

#if USE_TC
// ---------------- tcgen05 / cluster PTX (arch-specific passes only) ----------------
__device__ __forceinline__ uint32_t elect_one_pred() {
    uint32_t pred;
    asm volatile("{\n\t.reg .pred p;\n\telect.sync _|p, 0xFFFFFFFF;\n\tselp.b32 %0, 1, 0, p;\n\t}"
                 : "=r"(pred));
    return pred;
}
__device__ __forceinline__ uint32_t cluster_rank() {
    uint32_t r;
    asm("mov.u32 %0, %%cluster_ctarank;" : "=r"(r));
    return r;
}
#define CLUSTER_SYNC() do { \
    asm volatile("barrier.cluster.arrive.aligned;" ::: "memory"); \
    asm volatile("barrier.cluster.wait.aligned;" ::: "memory"); \
} while (0)
__device__ __forceinline__ float ld_dsmem_f32(uint32_t addr, uint32_t rank) {
    uint32_t ra;
    asm("mapa.shared::cluster.u32 %0, %1, %2;" : "=r"(ra) : "r"(addr), "r"(rank));
    float v;
    asm volatile("ld.shared::cluster.f32 %0, [%1];" : "=f"(v) : "r"(ra));
    return v;
}
#define TCGEN05_ALLOC_CG2(a, n) \
    asm volatile("tcgen05.alloc.cta_group::2.sync.aligned.shared::cta.b32 [%0], %1;" \
                 :: "r"((uint32_t)(a)), "r"((uint32_t)(n)) : "memory")
#define TCGEN05_DEALLOC_CG2(t, n) \
    asm volatile("tcgen05.dealloc.cta_group::2.sync.aligned.b32 %0, %1;" :: "r"(t), "r"((uint32_t)(n)))
#define TCGEN05_RELINQ_CG2() \
    asm volatile("tcgen05.relinquish_alloc_permit.cta_group::2.sync.aligned;")
#define TCGEN05_WAIT_LD()  asm volatile("tcgen05.wait::ld.sync.aligned;" ::: "memory")
#define TCGEN05_WAIT_ST()  asm volatile("tcgen05.wait::st.sync.aligned;" ::: "memory")
#define TCGEN05_FENCE_BEFORE() asm volatile("tcgen05.fence::before_thread_sync;" ::: "memory")
#define TCGEN05_FENCE_AFTER()  asm volatile("tcgen05.fence::after_thread_sync;" ::: "memory")
#define FENCE_PROXY() asm volatile("fence.proxy.async.shared::cta;" ::: "memory")
#define MBARRIER_INIT(m, c) \
    asm volatile("mbarrier.init.shared.b64 [%0], %1;" :: "r"((uint32_t)(m)), "r"((uint32_t)(c)) : "memory")
#define MBARRIER_INVAL(m) \
    asm volatile("mbarrier.inval.shared.b64 [%0];" :: "r"((uint32_t)(m)) : "memory")
#define MBARRIER_WAIT_PARITY(mb, ph) do { \
    uint32_t _m = (uint32_t)(mb); uint32_t _p = (uint32_t)(ph); uint32_t _d; \
    asm volatile("{\n\t.reg .pred p;\n\t" \
        "mbarrier.try_wait.parity.acquire.cta.shared::cta.b64 p, [%1], %2;\n\t" \
        "selp.b32 %0, 1, 0, p;\n\t}" : "=r"(_d) : "r"(_m), "r"(_p) : "memory"); \
    if (!_d) { \
        asm volatile("{\n\t.reg .pred P1;\n\t" \
            "WAIT_LOOP_%=:\n\t" \
            "mbarrier.try_wait.parity.acquire.cta.shared::cta.b64 P1, [%0], %1, 0x989680;\n\t" \
            "@P1 bra.uni WAIT_DONE_%=;\n\t" \
            "bra.uni WAIT_LOOP_%=;\n\t" \
            "WAIT_DONE_%=:\n\t}" :: "r"(_m), "r"(_p) : "memory"); \
    } \
} while (0)
#define TCGEN05_LD_X32(r, a) \
    asm volatile("tcgen05.ld.sync.aligned.32x32b.x32.b32 " \
        "{%0, %1, %2, %3, %4, %5, %6, %7, %8, %9, %10, %11, %12, %13, %14, %15, " \
        " %16, %17, %18, %19, %20, %21, %22, %23, %24, %25, %26, %27, %28, %29, %30, %31}, [%32];" \
        : "=r"((r)[0]),  "=r"((r)[1]),  "=r"((r)[2]),  "=r"((r)[3]), \
          "=r"((r)[4]),  "=r"((r)[5]),  "=r"((r)[6]),  "=r"((r)[7]), \
          "=r"((r)[8]),  "=r"((r)[9]),  "=r"((r)[10]), "=r"((r)[11]), \
          "=r"((r)[12]), "=r"((r)[13]), "=r"((r)[14]), "=r"((r)[15]), \
          "=r"((r)[16]), "=r"((r)[17]), "=r"((r)[18]), "=r"((r)[19]), \
          "=r"((r)[20]), "=r"((r)[21]), "=r"((r)[22]), "=r"((r)[23]), \
          "=r"((r)[24]), "=r"((r)[25]), "=r"((r)[26]), "=r"((r)[27]), \
          "=r"((r)[28]), "=r"((r)[29]), "=r"((r)[30]), "=r"((r)[31]) \
        : "r"(a))
#define TCGEN05_ST_X16(a, r) \
    asm volatile("tcgen05.st.sync.aligned.32x32b.x16.b32 [%0], " \
        "{%1, %2, %3, %4, %5, %6, %7, %8, %9, %10, %11, %12, %13, %14, %15, %16};" \
        :: "r"(a), \
           "r"((r)[0]),  "r"((r)[1]),  "r"((r)[2]),  "r"((r)[3]), \
           "r"((r)[4]),  "r"((r)[5]),  "r"((r)[6]),  "r"((r)[7]), \
           "r"((r)[8]),  "r"((r)[9]),  "r"((r)[10]), "r"((r)[11]), \
           "r"((r)[12]), "r"((r)[13]), "r"((r)[14]), "r"((r)[15]) \
        : "memory")

// cg2 bf16 TS MMA (A in TMEM, B in SMEM; 8-reg disable-output-lane = all enabled)
__device__ __forceinline__ void mma_bf16_ts_cg2(uint32_t d, uint32_t a, uint64_t b, uint32_t en) {
    asm volatile(
        "{\n\t.reg .pred p;\n\tsetp.ne.u32 p, %5, 0;\n\t"
        "tcgen05.mma.cta_group::2.kind::f16 [%0], [%1], %2, %3, "
        "{%4, %4, %4, %4, %4, %4, %4, %4}, p;\n\t}"
        :: "r"(d), "r"(a), "l"(b), "r"(IDESC2), "r"(0u), "r"(en) : "memory");
}
#define TCGEN05_COMMIT_MC2(mbar, mask) \
    asm volatile("tcgen05.commit.cta_group::2.mbarrier::arrive::one.shared::cluster.multicast::cluster.b64 [%0], %1;" \
                 :: "r"((uint32_t)(mbar)), "h"((uint16_t)(mask)) : "memory")

__device__ __forceinline__ uint64_t make_desc(uint32_t addr) {
    const uint64_t base = (uint64_t(2) << 61) | (uint64_t(1) << 46) |
                          (uint64_t(64) << 32) | (uint64_t(1) << 16);
    return base | ((uint64_t)(addr >> 4) & 0x3FFF);
}

// Inline split of my 64-row W half (raw fp32, row-major) into smem hi/lo tiles.
__device__ __forceinline__ void split_w_half(char* sm, const float* __restrict__ wsrc, int tid) {
#pragma unroll
    for (int it = 0; it < 2; ++it) {
        int idx = tid + it * THREADS;      // 0..1023 = 64 rows x 16 chunks
        int row = idx >> 4;
        int ch = idx & 15;
        const float* p = wsrc + row * 128 + ch * 8;
        float4 a = *(const float4*)p;
        float4 b = *(const float4*)(p + 4);
        float f[8] = {a.x, a.y, a.z, a.w, b.x, b.y, b.z, b.w};
        uint4 H, L;
        split8f(f, H, L);
        uint32_t off = swb64(row, ch * 8);
        *(uint4*)(sm + OFF_WHI + off) = H;
        *(uint4*)(sm + OFF_WLO + off) = L;
    }
}
#endif  // USE_TC

// ---------------- fallback helpers (compile-only on non-arch passes) ----------------
#if !USE_TC
#define AP 132
#define WP 130
#define SM_ACT_F (256 * AP)
#define SM_WT_F  (128 * WP)
__device__ __forceinline__ u64 pack2(float x) {
    u64 r;
    unsigned int xi = __float_as_uint(x);
    asm("mov.b64 %0, {%1, %1};" : "=l"(r) : "r"(xi));
    return r;
}
__device__ __forceinline__ void fma2(u64& d, u64 a, u64 b) {
    asm("fma.rn.f32x2 %0, %1, %2, %0;" : "+l"(d) : "l"(a), "l"(b));
}
__device__ __forceinline__ void unpack2(u64 v, float& lo, float& hi) {
    unsigned int a, b;
    asm("mov.b64 {%0, %1}, %2;" : "=r"(a), "=r"(b) : "l"(v));
    lo = __uint_as_float(a);
    hi = __uint_as_float(b);
}
__device__ __forceinline__ void load_wt(float* sm_wt, const float* __restrict__ w, int tid) {
    for (int idx = tid; idx < 128 * 32; idx += THREADS) {
        int j = idx >> 5;
        int kc = (idx & 31) << 2;
        float4 v = *(const float4*)(w + j * 128 + kc);
        sm_wt[(kc + 0) * WP + j] = v.x;
        sm_wt[(kc + 1) * WP + j] = v.y;
        sm_wt[(kc + 2) * WP + j] = v.z;
        sm_wt[(kc + 3) * WP + j] = v.w;
    }
}
__device__ __forceinline__ void fb_gemm(u64 (&acc)[8][4], const float* sm_act,
                                        const float* sm_wt, int m, int g) {
#pragma unroll
    for (int i = 0; i < 8; ++i)
#pragma unroll
        for (int p = 0; p < 4; ++p) acc[i][p] = 0ULL;
    const float* a0 = sm_act + (g * 8) * AP;
#pragma unroll 2
    for (int k = 0; k < 128; ++k) {
        const float* wk = sm_wt + k * WP + 2 * m;
        u64 b0 = *(const u64*)(wk);
        u64 b1 = *(const u64*)(wk + 32);
        u64 b2 = *(const u64*)(wk + 64);
        u64 b3 = *(const u64*)(wk + 96);
#pragma unroll
        for (int i = 0; i < 8; ++i) {
            u64 a2 = pack2(a0[i * AP + k]);
            fma2(acc[i][0], a2, b0);
            fma2(acc[i][1], a2, b1);
            fma2(acc[i][2], a2, b2);
            fma2(acc[i][3], a2, b3);
        }
    }
}
__device__ __forceinline__ void fb_bn_relu(u64 (&acc)[8][4], float* sm_act, float* sm_scr,
                                           float* sm_sc, float* sm_sh,
                                           const float* sm_gm, const float* sm_bt,
                                           int m, int g, int tid) {
    float* ssum = sm_scr;
    float* ssq  = sm_scr + 32 * 128;
    __syncthreads();
#pragma unroll
    for (int p = 0; p < 4; ++p) {
        int j0 = 2 * m + 32 * p;
        float s0 = 0.f, q0 = 0.f, s1 = 0.f, q1 = 0.f;
#pragma unroll
        for (int i = 0; i < 8; ++i) {
            float lo, hi;
            unpack2(acc[i][p], lo, hi);
            s0 += lo; q0 += lo * lo;
            s1 += hi; q1 += hi * hi;
        }
        ssum[g * 128 + j0] = s0;     ssq[g * 128 + j0] = q0;
        ssum[g * 128 + j0 + 1] = s1; ssq[g * 128 + j0 + 1] = q1;
    }
    __syncthreads();
    if (tid < 128) {
        float s = 0.f, q = 0.f;
#pragma unroll
        for (int gg = 0; gg < 32; ++gg) {
            s += ssum[gg * 128 + tid];
            q += ssq[gg * 128 + tid];
        }
        float mean = s * (1.0f / 256.0f);
        float var  = q * (1.0f / 256.0f) - mean * mean;
        float inv  = rsqrtf(var + 1e-5f);
        float sc   = sm_gm[tid] * inv;
        sm_sc[tid] = sc;
        sm_sh[tid] = sm_bt[tid] - mean * sc;
    }
    __syncthreads();
#pragma unroll
    for (int p = 0; p < 4; ++p) {
        int j0 = 2 * m + 32 * p;
        float sc0 = sm_sc[j0], sh0 = sm_sh[j0];
        float sc1 = sm_sc[j0 + 1], sh1 = sm_sh[j0 + 1];
#pragma unroll
        for (int i = 0; i < 8; ++i) {
            float lo, hi;
            unpack2(acc[i][p], lo, hi);
            float2 v;
            v.x = fmaxf(fmaf(lo, sc0, sh0), 0.0f);
            v.y = fmaxf(fmaf(hi, sc1, sh1), 0.0f);
            *(float2*)(sm_act + (g * 8 + i) * AP + j0) = v;
        }
    }
}
#endif  // !USE_TC

// ============================= the MLP kernel =============================
__global__ void __launch_bounds__(THREADS, 2) __cluster_dims__(2, 1, 1)
mlp_kernel(const float* __restrict__ s, const float* __restrict__ c,
           const float* __restrict__ sw1, const float* __restrict__ sg1, const float* __restrict__ sbe1,
           const float* __restrict__ sw2, const float* __restrict__ sg2, const float* __restrict__ sbe2,
           const float* __restrict__ sw3, const float* __restrict__ sb3,
           const float* __restrict__ cw1, const float* __restrict__ cg1, const float* __restrict__ cbe1,
           const float* __restrict__ cw2, const float* __restrict__ cg2, const float* __restrict__ cbe2,
           const float* __restrict__ cw3, const float* __restrict__ cb3,
           float* __restrict__ out) {
    extern __shared__ char smc[];
    const int tid = threadIdx.x;
    const bool is_c = ((blockIdx.x >> 1) == 0);
    const int slice = (int)(blockIdx.x >> 1) - 1;

    const float *W1, *W2, *W3, *G1, *G2, *B1, *B2, *B3;
    if (is_c) { W1=cw1; W2=cw2; W3=cw3; G1=cg1; G2=cg2; B1=cbe1; B2=cbe2; B3=cb3; }
    else      { W1=sw1; W2=sw2; W3=sw3; G1=sg1; G2=sg2; B1=sbe1; B2=sbe2; B3=sb3; }

#if USE_TC
    // ======================= cg2 tcgen05 TS path =======================
    char* sm = smc;
    const uint32_t smb = smem_u32(sm);
    const int wid = tid >> 5;
    const int lane = tid & 31;
    const uint32_t rank = cluster_rank();
    const uint32_t peer = rank ^ 1u;
    const int wrow0 = (int)rank * 64 * 128;   // my W half offset (rows rank*64..)

    if (wid == 0) {
        TCGEN05_ALLOC_CG2(smb + OFF_TMEM, TMEM_COLS);
        TCGEN05_RELINQ_CG2();
    }
    if (tid == 0) MBARRIER_INIT(smb + OFF_MBAR, 1);
    __syncthreads();
    uint32_t tmem;
    asm volatile("ld.shared.b32 %0, [%1];" : "=r"(tmem) : "r"(smb + OFF_TMEM));

    const int rowgrp = wid & 3;               // = physical subpartition
    const int colgrp = wid >> 2;
    const int lrow = rowgrp * 32 + lane;      // local A row 0..127
    const int jbase = colgrp * 32;            // my 32 output columns
    const uint32_t woff = (uint32_t)rowgrp << 21;

    float* rawf = (float*)(sm + OFF_RAW);
    float* scv = (float*)(sm + OFF_SC);
    float* shv = (float*)(sm + OFF_SH);
    float* pst = (float*)(sm + OFF_PST);
    const uint32_t pst_addr = smb + OFF_PST;

    // ---- Stage input: coalesced gmem -> raw smem (pitch 132 floats) ----
    {
#pragma unroll
        for (int it = 0; it < 4; ++it) {
            int idx = tid + it * THREADS;
            int row = idx >> 4;
            int ch = idx & 15;
            int grow = (int)rank * 128 + row;
            const float* p = is_c ? (c + (size_t)grow * 128 + ch * 8)
                                  : (s + ((size_t)grow * 512 + slice) * 128 + ch * 8);
            float4 a = *(const float4*)p;
            float4 b = *(const float4*)(p + 4);
            *(float4*)(rawf + row * 132 + ch * 8) = a;
            *(float4*)(rawf + row * 132 + ch * 8 + 4) = b;
        }
    }
    split_w_half(sm, W1 + wrow0, tid);
    FENCE_PROXY();
    __syncthreads();

    // ---- raw smem -> split -> STTM into A_hi/A_lo (my row, my 32 cols) ----
    {
        uint32_t hi[16], lo[16];
        const float* rp = rawf + lrow * 132 + jbase;
#pragma unroll
        for (int pr = 0; pr < 16; ++pr) {
            float2 xy = *(const float2*)(rp + 2 * pr);
            split_pair(xy.x, xy.y, hi[pr], lo[pr]);
        }
        TCGEN05_ST_X16(tmem + TM_AH + colgrp * 16 + woff, hi);
        TCGEN05_ST_X16(tmem + TM_AL + colgrp * 16 + woff, lo);
        TCGEN05_WAIT_ST();
        TCGEN05_FENCE_BEFORE();
    }

    uint32_t d[32];

#pragma unroll 1
    for (int layer = 0; layer < 3; ++layer) {
        // A (TMEM) + W (smem) ready cluster-wide before MMA
        CLUSTER_SYNC();

        if (rank == 0 && wid == 0) {
            TCGEN05_FENCE_AFTER();
            if (elect_one_pred()) {
                uint64_t bh = make_desc(smb + OFF_WHI);
                uint64_t bl = make_desc(smb + OFF_WLO);
#pragma unroll
                for (int pass = 0; pass < 3; ++pass) {
                    uint32_t acol = (pass == 2) ? (tmem + TM_AL) : (tmem + TM_AH);
                    uint64_t bd = (pass == 1) ? bl : bh;
#pragma unroll
                    for (int ks = 0; ks < 8; ++ks) {
                        uint32_t boff = ((ks >> 2) << 9) + ((ks & 3) << 1);
                        mma_bf16_ts_cg2(tmem + TM_D, acol + ks * 8, bd + boff,
                                        (pass | ks) ? 1u : 0u);
                    }
                }
                TCGEN05_COMMIT_MC2(smb + OFF_MBAR, 0x3);
            }
        }
        MBARRIER_WAIT_PARITY(smb + OFF_MBAR, layer & 1);
        TCGEN05_FENCE_AFTER();

        TCGEN05_LD_X32(d, tmem + TM_D + jbase);

        // split next-layer W half (MMA chain done -> W smem free); overlaps LDTM
        if (layer < 2) {
            split_w_half(sm, (layer == 0 ? W2 : W3) + wrow0, tid);
            FENCE_PROXY();
        }
        TCGEN05_WAIT_LD();
        TCGEN05_FENCE_BEFORE();

        if (layer < 2) {
            // ---- per-warp (sum, sumsq) over 32 rows via butterfly transpose ----
            {
                float s16[16];
#pragma unroll
                for (int i = 0; i < 16; ++i) {
                    float dlo = __uint_as_float(d[i]);
                    float dhi = __uint_as_float(d[16 + i]);
                    bool up = (lane & 16);
                    float dk = up ? dhi : dlo;
                    float ds = up ? dlo : dhi;
                    s16[i] = dk + __shfl_xor_sync(0xFFFFFFFFu, ds, 16);
                }
                float s8[8];
#pragma unroll
                for (int i = 0; i < 8; ++i) {
                    bool up = (lane & 8);
                    float k = up ? s16[8 + i] : s16[i];
                    float sn = up ? s16[i] : s16[8 + i];
                    s8[i] = k + __shfl_xor_sync(0xFFFFFFFFu, sn, 8);
                }
                float s4[4];
#pragma unroll
                for (int i = 0; i < 4; ++i) {
                    bool up = (lane & 4);
                    float k = up ? s8[4 + i] : s8[i];
                    float sn = up ? s8[i] : s8[4 + i];
                    s4[i] = k + __shfl_xor_sync(0xFFFFFFFFu, sn, 4);
                }
                float s2[2];
#pragma unroll
                for (int i = 0; i < 2; ++i) {
                    bool up = (lane & 2);
                    float k = up ? s4[2 + i] : s4[i];
                    float sn = up ? s4[i] : s4[2 + i];
                    s2[i] = k + __shfl_xor_sync(0xFFFFFFFFu, sn, 2);
                }
                {
                    bool up = (lane & 1);
                    float k = up ? s2[1] : s2[0];
                    float sn = up ? s2[0] : s2[1];
                    float s1 = k + __shfl_xor_sync(0xFFFFFFFFu, sn, 1);
                    pst[rowgrp * 128 + jbase + lane] = s1;
                }
                float q16[16];
#pragma unroll
                for (int i = 0; i < 16; ++i) {
                    float dlo = __uint_as_float(d[i]);
                    float dhi = __uint_as_float(d[16 + i]);
                    bool up = (lane & 16);
                    float dk = up ? dhi : dlo;
                    float ds = up ? dlo : dhi;
                    float rv = __shfl_xor_sync(0xFFFFFFFFu, ds, 16);
                    q16[i] = fmaf(dk, dk, rv * rv);
                }
                float q8[8];
#pragma unroll
                for (int i = 0; i < 8; ++i) {
                    bool up = (lane & 8);
                    float k = up ? q16[8 + i] : q16[i];
                    float sn = up ? q16[i] : q16[8 + i];
                    q8[i] = k + __shfl_xor_sync(0xFFFFFFFFu, sn, 8);
                }
                float q4[4];
#pragma unroll
                for (int i = 0; i < 4; ++i) {
                    bool up = (lane & 4);
                    float k = up ? q8[4 + i] : q8[i];
                    float sn = up ? q8[i] : q8[4 + i];
                    q4[i] = k + __shfl_xor_sync(0xFFFFFFFFu, sn, 4);
                }
                float q2[2];
#pragma unroll
                for (int i = 0; i < 2; ++i) {
                    bool up = (lane & 2);
                    float k = up ? q4[2 + i] : q4[i];
                    float sn = up ? q4[i] : q4[2 + i];
                    q2[i] = k + __shfl_xor_sync(0xFFFFFFFFu, sn, 2);
                }
                {
                    bool up = (lane & 1);
                    float k = up ? q2[1] : q2[0];
                    float sn = up ? q2[0] : q2[1];
                    float q1 = k + __shfl_xor_sync(0xFFFFFFFFu, sn, 1);
                    pst[512 + rowgrp * 128 + jbase + lane] = q1;
                }
            }
            // both CTAs' partials visible cluster-wide
            CLUSTER_SYNC();

            if (tid < 128) {
                float ss = pst[tid] + pst[128 + tid] + pst[256 + tid] + pst[384 + tid];
                float qq = pst[512 + tid] + pst[640 + tid] + pst[768 + tid] + pst[896 + tid];
#pragma unroll
                for (int k = 0; k < 4; ++k) {
                    ss += ld_dsmem_f32(pst_addr + (uint32_t)(k * 128 + tid) * 4u, peer);
                    qq += ld_dsmem_f32(pst_addr + (uint32_t)(512 + k * 128 + tid) * 4u, peer);
                }
                float mean = ss * (1.0f / 256.0f);
                float var = qq * (1.0f / 256.0f) - mean * mean;
                float inv = rsqrtf(var + 1e-5f);
                float gm = __ldg((layer ? G2 : G1) + tid);
                float bt = __ldg((layer ? B2 : B1) + tid);
                float scl = gm * inv;
                scv[tid] = scl;
                shv[tid] = bt - mean * scl;   // linear bias cancels in BN
            }
            __syncthreads();

            // normalize + ReLU, split, STTM into A_hi/A_lo (next layer A)
            {
                uint32_t hi[16], lo[16];
#pragma unroll
                for (int pr = 0; pr < 16; ++pr) {
                    int j = jbase + 2 * pr;
                    float x = fmaxf(fmaf(__uint_as_float(d[2 * pr]), scv[j], shv[j]), 0.f);
                    float y = fmaxf(fmaf(__uint_as_float(d[2 * pr + 1]), scv[j + 1], shv[j + 1]), 0.f);
                    split_pair(x, y, hi[pr], lo[pr]);
                }
                TCGEN05_ST_X16(tmem + TM_AH + colgrp * 16 + woff, hi);
                TCGEN05_ST_X16(tmem + TM_AL + colgrp * 16 + woff, lo);
                TCGEN05_WAIT_ST();
                TCGEN05_FENCE_BEFORE();
            }
            // next iteration's CLUSTER_SYNC orders A'/W for the next MMA
        }
    }

    // ---- layer-3 epilogue: +b3, gate, write ----
    const int grow = (int)rank * 128 + lrow;
    const int q0 = jbase >> 2;
    if (is_c) {
#pragma unroll
        for (int q = 0; q < 8; ++q) {
            float4 bb = __ldg((const float4*)B3 + q0 + q);
            float4 v;
            v.x = __uint_as_float(d[4 * q + 0]) + bb.x;
            v.y = __uint_as_float(d[4 * q + 1]) + bb.y;
            v.z = __uint_as_float(d[4 * q + 2]) + bb.z;
            v.w = __uint_as_float(d[4 * q + 3]) + bb.w;
            g_c_out[grow * 32 + q0 + q] = v;
        }
        __threadfence();
        CLUSTER_SYNC();   // both c-CTAs' writes done
        if (rank == 0 && tid == 0) atomicExch(&g_flag, 1);
    } else {
        if (tid == 0) {
            while (atomicAdd(&g_flag, 0) == 0) { __nanosleep(64); }
            __threadfence();
        }
        __syncthreads();
        float* op = out + ((size_t)grow * 512 + slice) * 128 + jbase;
#pragma unroll
        for (int q = 0; q < 8; ++q) {
            float4 bb = __ldg((const float4*)B3 + q0 + q);
            float4 cv = __ldcg(&g_c_out[grow * 32 + q0 + q]);
            float4 v;
            v.x = (__uint_as_float(d[4 * q + 0]) + bb.x) * cv.x;
            v.y = (__uint_as_float(d[4 * q + 1]) + bb.y) * cv.y;
            v.z = (__uint_as_float(d[4 * q + 2]) + bb.z) * cv.z;
            v.w = (__uint_as_float(d[4 * q + 3]) + bb.w) * cv.w;
            ((float4*)op)[q] = v;
        }
    }

    CLUSTER_SYNC();
    if (tid == 0) MBARRIER_INVAL(smb + OFF_MBAR);
    __syncthreads();
    if (wid == 0) TCGEN05_DEALLOC_CG2(tmem, TMEM_COLS);

#else
    // ============== FFMA2 fallback (compile-only; sm_103a SASS always runs) ==============
    if (blockIdx.x & 1) return;
    float* smf = (float*)smc;
    float* sm_act = smf;
    float* sm_wt  = smf + SM_ACT_F;
    float* sm_sc  = sm_wt + SM_WT_F;
    float* sm_sh  = sm_sc + 128;
    float* sm_gm  = sm_sh + 128;
    float* sm_bt  = sm_gm + 128;
    const int m = tid & 15;
    const int g = tid >> 4;

    {
        const float* src = is_c ? c : (s + (size_t)slice * 128);
        const size_t rstride = is_c ? (size_t)128 : (size_t)512 * 128;
        for (int idx = tid; idx < 256 * 32; idx += THREADS) {
            int r = idx >> 5;
            int kc = (idx & 31) << 2;
            float4 v = *(const float4*)(src + (size_t)r * rstride + kc);
            *(float4*)(sm_act + r * AP + kc) = v;
        }
    }
    load_wt(sm_wt, W1, tid);
    if (tid < 128) { sm_gm[tid] = G1[tid]; sm_bt[tid] = B1[tid]; }
    __syncthreads();

    u64 acc[8][4];
    fb_gemm(acc, sm_act, sm_wt, m, g);
    fb_bn_relu(acc, sm_act, sm_wt, sm_sc, sm_sh, sm_gm, sm_bt, m, g, tid);
    load_wt(sm_wt, W2, tid);
    if (tid < 128) { sm_gm[tid] = G2[tid]; sm_bt[tid] = B2[tid]; }
    __syncthreads();

    fb_gemm(acc, sm_act, sm_wt, m, g);
    fb_bn_relu(acc, sm_act, sm_wt, sm_sc, sm_sh, sm_gm, sm_bt, m, g, tid);
    load_wt(sm_wt, W3, tid);
    if (tid < 128) sm_bt[tid] = B3[tid];
    __syncthreads();

    fb_gemm(acc, sm_act, sm_wt, m, g);

    float* gco = (float*)g_c_out;
    if (is_c) {
#pragma unroll
        for (int p = 0; p < 4; ++p) {
            int j0 = 2 * m + 32 * p;
            float bb0 = sm_bt[j0], bb1 = sm_bt[j0 + 1];
#pragma unroll
            for (int i = 0; i < 8; ++i) {
                float lo, hi;
                unpack2(acc[i][p], lo, hi);
                float2 v; v.x = lo + bb0; v.y = hi + bb1;
                *(float2*)&gco[(g * 8 + i) * 128 + j0] = v;
            }
        }
        __threadfence();
        __syncthreads();
        if (tid == 0) atomicExch(&g_flag, 1);
    } else {
        if (tid == 0) {
            while (atomicAdd(&g_flag, 0) == 0) { }
            __threadfence();
        }
        __syncthreads();
#pragma unroll
        for (int p = 0; p < 4; ++p) {
            int j0 = 2 * m + 32 * p;
            float bb0 = sm_bt[j0], bb1 = sm_bt[j0 + 1];
#pragma unroll
            for (int i = 0; i < 8; ++i) {
                int r = g * 8 + i;
                float lo, hi;
                unpack2(acc[i][p], lo, hi);
                float2 cv = __ldcg((const float2*)&gco[r * 128 + j0]);
                float2 v;
                v.x = (lo + bb0) * cv.x;
                v.y = (hi + bb1) * cv.y;
                *(float2*)(out + ((size_t)r * 512 + slice) * 128 + j0) = v;
            }
        }
    }
#endif
}

// ---- Max-pool stage 1: grid 1024 = b(256) x seg(4, 128 slices each) ----
__global__ void __launch_bounds__(256, 8)
partial_max(const float* __restrict__ so) {
    __shared__ float4 red[8][32];
    int b = blockIdx.x >> 2;
    int seg = blockIdx.x & 3;
    int c4 = threadIdx.x & 31;
    int sub = threadIdx.x >> 5;
    const float4* p = (const float4*)(so + ((size_t)b * 512 + seg * 128 + sub * 16) * 128) + c4;
    float4 mx = make_float4(-3.4e38f, -3.4e38f, -3.4e38f, -3.4e38f);
#pragma unroll 16
    for (int i = 0; i < 16; ++i) {
        float4 v = p[(size_t)i * 32];
        mx.x = fmaxf(mx.x, v.x); mx.y = fmaxf(mx.y, v.y);
        mx.z = fmaxf(mx.z, v.z); mx.w = fmaxf(mx.w, v.w);
    }
    red[sub][c4] = mx;
    __syncthreads();
    if (threadIdx.x < 32) {
        float4 r = red[0][c4];
#pragma unroll
        for (int ss = 1; ss < 8; ++ss) {
            float4 v = red[ss][c4];
            r.x = fmaxf(r.x, v.x); r.y = fmaxf(r.y, v.y);
            r.z = fmaxf(r.z, v.z); r.w = fmaxf(r.w, v.w);
        }
        g_part[(size_t)blockIdx.x * 32 + c4] = r;
    }
}

// ---- Max-pool stage 2; also resets flag for graph replay ----
__global__ void final_max(float* __restrict__ agg) {
    if (blockIdx.x == 0 && threadIdx.x == 0) g_flag = 0;
    int idx = blockIdx.x * 256 + threadIdx.x;
    int b = idx >> 5;
    int c4 = idx & 31;
    float4 r = g_part[(size_t)(b * 4) * 32 + c4];
#pragma unroll
    for (int seg = 1; seg < 4; ++seg) {
        float4 v = g_part[(size_t)(b * 4 + seg) * 32 + c4];
        r.x = fmaxf(r.x, v.x); r.y = fmaxf(r.y, v.y);
        r.z = fmaxf(r.z, v.z); r.w = fmaxf(r.w, v.w);
    }
    ((float4*)agg)[idx] = r;
}

extern "C" void kernel_launch(void* const* d_in, const int* in_sizes, int n_in,
                              void* d_out, int out_size) {
    const float* s    = (const float*)d_in[0];
    const float* c    = (const float*)d_in[1];
    const float* sw1  = (const float*)d_in[2];
    const float* sg1  = (const float*)d_in[4];
    const float* sbe1 = (const float*)d_in[5];
    const float* sw2  = (const float*)d_in[6];
    const float* sg2  = (const float*)d_in[8];
    const float* sbe2 = (const float*)d_in[9];
    const float* sw3  = (const float*)d_in[10];
    const float* sb3  = (const float*)d_in[11];
    const float* cw1  = (const float*)d_in[12];
    const float* cg1  = (const float*)d_in[14];
    const float* cbe1 = (const float*)d_in[15];
    const float* cw2  = (const float*)d_in[16];
    const float* cg2  = (const float*)d_in[18];
    const float* cbe2 = (const float*)d_in[19];
    const float* cw3  = (const float*)d_in[20];
    const float* cb3  = (const float*)d_in[21];
    float* out = (float*)d_out;

    cudaFuncSetAttribute(mlp_kernel, cudaFuncAttributeMaxDynamicSharedMemorySize, SM_TC_BYTES);

    // 513 clusters x 2 CTAs: cluster 0 = c-path, clusters 1..512 = slices
    mlp_kernel<<<1026, THREADS, SM_TC_BYTES>>>(s, c,
                                               sw1, sg1, sbe1, sw2, sg2, sbe2, sw3, sb3,
                                               cw1, cg1, cbe1, cw2, cg2, cbe2, cw3, cb3,
                                               out);

    float* agg = out + ((size_t)out_size - 256 * 128);
    partial_max<<<1024, 256>>>(out);
    final_max<<<32, 256>>>(agg);
}

// round 16
// speedup vs baseline: 1.0737x; 1.0737x over previous
#include <cuda_runtime.h>
#include <cuda_bf16.h>
#include <cstdint>

// CGBlock: per-slice 3-layer MLP (Linear->BN->ReLU x2 ->Linear), context gate,
// max-pool. B=256, S=512, D=128 fp32.
// cta_group::2 bf16x3-split SS MMA (M=256 per 2-CTA cluster), 2 CTAs/SM.
// R16 = R10 (138us baseline) + N=64 dual-mbarrier MMA split: first D-half
// warps start LDTM under the second chain's MMA tail. cg2 N=64 permutes
// logical output columns per colgrp as {0,64,32,96}; handled via jout remap.

#define THREADS 512

#if defined(__CUDA_ARCH__) && (defined(__CUDA_ARCH_FEAT_SM103_ALL) || defined(__CUDA_ARCH_FEAT_SM100_ALL) || defined(__CUDA_ARCH_FEAT_SM101_ALL))
#define USE_TC 1
#else
#define USE_TC 0
#endif

// ---------------- shared device state ----------------
__device__ float4 g_c_out[256 * 32];
__device__ int g_flag = 0;
__device__ float4 g_part[1024 * 32];

// ---------------- TC-path SMEM layout (bytes) ----------------
#define OFF_TMEM 0
#define OFF_MBAR 8
#define OFF_MBAR2 16
#define OFF_AHI  1024      // A_hi: 128r x 128k bf16 blocked-SW128 = 32768
#define OFF_ALO  33792     // A_lo: 32768
#define OFF_WHI  66560     // W_hi half: 64r x 128k = 16384
#define OFF_WLO  82944     // W_lo half: 16384
#define OFF_SC   99328     // BN scale f32[128]
#define OFF_SH   99840     // BN shift f32[128]
#define OFF_PST  100352    // f32[1024]: 512 sum + 512 sumsq partials
#define SM_TC_BYTES 104448

// idesc kind::f16 cg2: c=F32, a=BF16, b=BF16, N=64, M=256
#define IDESC_N64 0x10100490u

typedef unsigned long long u64;

__device__ __forceinline__ uint32_t smem_u32(const void* p) {
    uint32_t a;
    asm("{ .reg .u64 t; cvta.to.shared.u64 t, %1; cvt.u32.u64 %0, t; }" : "=r"(a) : "l"(p));
    return a;
}

// Blocked SW128 addr, 128-row bf16 tile (16 atom-rows x 2 atom-cols).
__device__ __forceinline__ uint32_t swb(int rl, int j0) {
    uint32_t off = (uint32_t)((((rl >> 3) + ((j0 >> 6) << 4)) << 10) + ((rl & 7) << 7) + ((j0 & 63) << 1));
    return off ^ ((off >> 3) & 0x70);
}
// Blocked SW128 addr, 64-row bf16 tile (8 atom-rows x 2 atom-cols).
__device__ __forceinline__ uint32_t swb64(int rl, int j0) {
    uint32_t off = (uint32_t)((((rl >> 3) + ((j0 >> 6) << 3)) << 10) + ((rl & 7) << 7) + ((j0 & 63) << 1));
    return off ^ ((off >> 3) & 0x70);
}

// Fast split: hi = bf16-truncate (PRMT pack), lo = rn_bf16(x - hi).
__device__ __forceinline__ void split_pair(float x, float y, uint32_t& h, uint32_t& l) {
    uint32_t bx = __float_as_uint(x), by = __float_as_uint(y);
    asm("prmt.b32 %0, %1, %2, 0x7632;" : "=r"(h) : "r"(bx), "r"(by));
    float lx = x - __uint_as_float(bx & 0xFFFF0000u);
    float ly = y - __uint_as_float(by & 0xFFFF0000u);
    asm("cvt.rn.bf16x2.f32 %0, %1, %2;" : "=r"(l) : "f"(ly), "f"(lx));
}
__device__ __forceinline__ void split8f(const float* f, uint4& h, uint4& l) {
    uint32_t hh[4], ll[4];
#pragma unroll
    for (int i = 0; i < 4; ++i) split_pair(f[2 * i], f[2 * i + 1], hh[i], ll[i]);
    h = make_uint4(hh[0], hh[1], hh[2], hh[3]);
    l = make_uint4(ll[0], ll[1], ll[2], ll[3]);
}

#if USE_TC
// ---------------- tcgen05 / cluster PTX (arch-specific passes only) ----------------
__device__ __forceinline__ uint32_t elect_one_pred() {
    uint32_t pred;
    asm volatile("{\n\t.reg .pred p;\n\telect.sync _|p, 0xFFFFFFFF;\n\tselp.b32 %0, 1, 0, p;\n\t}"
                 : "=r"(pred));
    return pred;
}
__device__ __forceinline__ uint32_t cluster_rank() {
    uint32_t r;
    asm("mov.u32 %0, %%cluster_ctarank;" : "=r"(r));
    return r;
}
#define CLUSTER_SYNC() do { \
    asm volatile("barrier.cluster.arrive.aligned;" ::: "memory"); \
    asm volatile("barrier.cluster.wait.aligned;" ::: "memory"); \
} while (0)
__device__ __forceinline__ float ld_dsmem_f32(uint32_t addr, uint32_t rank) {
    uint32_t ra;
    asm("mapa.shared::cluster.u32 %0, %1, %2;" : "=r"(ra) : "r"(addr), "r"(rank));
    float v;
    asm volatile("ld.shared::cluster.f32 %0, [%1];" : "=f"(v) : "r"(ra));
    return v;
}
#define TCGEN05_ALLOC_CG2(a, n) \
    asm volatile("tcgen05.alloc.cta_group::2.sync.aligned.shared::cta.b32 [%0], %1;" \
                 :: "r"((uint32_t)(a)), "r"((uint32_t)(n)) : "memory")
#define TCGEN05_DEALLOC_CG2(t, n) \
    asm volatile("tcgen05.dealloc.cta_group::2.sync.aligned.b32 %0, %1;" :: "r"(t), "r"((uint32_t)(n)))
#define TCGEN05_RELINQ_CG2() \
    asm volatile("tcgen05.relinquish_alloc_permit.cta_group::2.sync.aligned;")
#define TCGEN05_WAIT_LD()  asm volatile("tcgen05.wait::ld.sync.aligned;" ::: "memory")
#define TCGEN05_FENCE_BEFORE() asm volatile("tcgen05.fence::before_thread_sync;" ::: "memory")
#define TCGEN05_FENCE_AFTER()  asm volatile("tcgen05.fence::after_thread_sync;" ::: "memory")
#define FENCE_PROXY() asm volatile("fence.proxy.async.shared::cta;" ::: "memory")
#define MBARRIER_INIT(m, c) \
    asm volatile("mbarrier.init.shared.b64 [%0], %1;" :: "r"((uint32_t)(m)), "r"((uint32_t)(c)) : "memory")
#define MBARRIER_INVAL(m) \
    asm volatile("mbarrier.inval.shared.b64 [%0];" :: "r"((uint32_t)(m)) : "memory")
#define MBARRIER_WAIT_PARITY(mb, ph) do { \
    uint32_t _m = (uint32_t)(mb); uint32_t _p = (uint32_t)(ph); uint32_t _d; \
    asm volatile("{\n\t.reg .pred p;\n\t" \
        "mbarrier.try_wait.parity.acquire.cta.shared::cta.b64 p, [%1], %2;\n\t" \
        "selp.b32 %0, 1, 0, p;\n\t}" : "=r"(_d) : "r"(_m), "r"(_p) : "memory"); \
    if (!_d) { \
        asm volatile("{\n\t.reg .pred P1;\n\t" \
            "WAIT_LOOP_%=:\n\t" \
            "mbarrier.try_wait.parity.acquire.cta.shared::cta.b64 P1, [%0], %1, 0x989680;\n\t" \
            "@P1 bra.uni WAIT_DONE_%=;\n\t" \
            "bra.uni WAIT_LOOP_%=;\n\t" \
            "WAIT_DONE_%=:\n\t}" :: "r"(_m), "r"(_p) : "memory"); \
    } \
} while (0)
#define TCGEN05_LD_X32(r, a) \
    asm volatile("tcgen05.ld.sync.aligned.32x32b.x32.b32 " \
        "{%0, %1, %2, %3, %4, %5, %6, %7, %8, %9, %10, %11, %12, %13, %14, %15, " \
        " %16, %17, %18, %19, %20, %21, %22, %23, %24, %25, %26, %27, %28, %29, %30, %31}, [%32];" \
        : "=r"((r)[0]),  "=r"((r)[1]),  "=r"((r)[2]),  "=r"((r)[3]), \
          "=r"((r)[4]),  "=r"((r)[5]),  "=r"((r)[6]),  "=r"((r)[7]), \
          "=r"((r)[8]),  "=r"((r)[9]),  "=r"((r)[10]), "=r"((r)[11]), \
          "=r"((r)[12]), "=r"((r)[13]), "=r"((r)[14]), "=r"((r)[15]), \
          "=r"((r)[16]), "=r"((r)[17]), "=r"((r)[18]), "=r"((r)[19]), \
          "=r"((r)[20]), "=r"((r)[21]), "=r"((r)[22]), "=r"((r)[23]), \
          "=r"((r)[24]), "=r"((r)[25]), "=r"((r)[26]), "=r"((r)[27]), \
          "=r"((r)[28]), "=r"((r)[29]), "=r"((r)[30]), "=r"((r)[31]) \
        : "r"(a))

// cg2 bf16 SS MMA, N=64 (8-reg disable-output-lane = all enabled)
__device__ __forceinline__ void mma_bf16_cg2_n64(uint32_t d, uint64_t a, uint64_t b, uint32_t en) {
    asm volatile(
        "{\n\t.reg .pred p;\n\tsetp.ne.u32 p, %5, 0;\n\t"
        "tcgen05.mma.cta_group::2.kind::f16 [%0], %1, %2, %3, "
        "{%4, %4, %4, %4, %4, %4, %4, %4}, p;\n\t}"
        :: "r"(d), "l"(a), "l"(b), "r"(IDESC_N64), "r"(0u), "r"(en) : "memory");
}
#define TCGEN05_COMMIT_MC2(mbar, mask) \
    asm volatile("tcgen05.commit.cta_group::2.mbarrier::arrive::one.shared::cluster.multicast::cluster.b64 [%0], %1;" \
                 :: "r"((uint32_t)(mbar)), "h"((uint16_t)(mask)) : "memory")

__device__ __forceinline__ uint64_t make_desc(uint32_t addr) {
    const uint64_t base = (uint64_t(2) << 61) | (uint64_t(1) << 46) |
                          (uint64_t(64) << 32) | (uint64_t(1) << 16);
    return base | ((uint64_t)(addr >> 4) & 0x3FFF);
}

// Inline split of my 64-row W half (raw fp32, row-major) into smem hi/lo tiles.
// Executed by tid0..nthr-1 of the calling subset (tbase subtracted by caller).
__device__ __forceinline__ void split_w_half_sub(char* sm, const float* __restrict__ wsrc,
                                                 int t, int nthr) {
    for (int idx = t; idx < 1024; idx += nthr) {   // 64 rows x 16 chunks
        int row = idx >> 4;
        int ch = idx & 15;
        const float* p = wsrc + row * 128 + ch * 8;
        float4 a = *(const float4*)p;
        float4 b = *(const float4*)(p + 4);
        float f[8] = {a.x, a.y, a.z, a.w, b.x, b.y, b.z, b.w};
        uint4 H, L;
        split8f(f, H, L);
        uint32_t off = swb64(row, ch * 8);
        *(uint4*)(sm + OFF_WHI + off) = H;
        *(uint4*)(sm + OFF_WLO + off) = L;
    }
}
#endif  // USE_TC

// ---------------- fallback helpers (compile-only on non-arch passes) ----------------
#if !USE_TC
#define AP 132
#define WP 130
#define SM_ACT_F (256 * AP)
#define SM_WT_F  (128 * WP)
__device__ __forceinline__ u64 pack2(float x) {
    u64 r;
    unsigned int xi = __float_as_uint(x);
    asm("mov.b64 %0, {%1, %1};" : "=l"(r) : "r"(xi));
    return r;
}
__device__ __forceinline__ void fma2(u64& d, u64 a, u64 b) {
    asm("fma.rn.f32x2 %0, %1, %2, %0;" : "+l"(d) : "l"(a), "l"(b));
}
__device__ __forceinline__ void unpack2(u64 v, float& lo, float& hi) {
    unsigned int a, b;
    asm("mov.b64 {%0, %1}, %2;" : "=r"(a), "=r"(b) : "l"(v));
    lo = __uint_as_float(a);
    hi = __uint_as_float(b);
}
__device__ __forceinline__ void load_wt(float* sm_wt, const float* __restrict__ w, int tid) {
    for (int idx = tid; idx < 128 * 32; idx += THREADS) {
        int j = idx >> 5;
        int kc = (idx & 31) << 2;
        float4 v = *(const float4*)(w + j * 128 + kc);
        sm_wt[(kc + 0) * WP + j] = v.x;
        sm_wt[(kc + 1) * WP + j] = v.y;
        sm_wt[(kc + 2) * WP + j] = v.z;
        sm_wt[(kc + 3) * WP + j] = v.w;
    }
}
__device__ __forceinline__ void fb_gemm(u64 (&acc)[8][4], const float* sm_act,
                                        const float* sm_wt, int m, int g) {
#pragma unroll
    for (int i = 0; i < 8; ++i)
#pragma unroll
        for (int p = 0; p < 4; ++p) acc[i][p] = 0ULL;
    const float* a0 = sm_act + (g * 8) * AP;
#pragma unroll 2
    for (int k = 0; k < 128; ++k) {
        const float* wk = sm_wt + k * WP + 2 * m;
        u64 b0 = *(const u64*)(wk);
        u64 b1 = *(const u64*)(wk + 32);
        u64 b2 = *(const u64*)(wk + 64);
        u64 b3 = *(const u64*)(wk + 96);
#pragma unroll
        for (int i = 0; i < 8; ++i) {
            u64 a2 = pack2(a0[i * AP + k]);
            fma2(acc[i][0], a2, b0);
            fma2(acc[i][1], a2, b1);
            fma2(acc[i][2], a2, b2);
            fma2(acc[i][3], a2, b3);
        }
    }
}
__device__ __forceinline__ void fb_bn_relu(u64 (&acc)[8][4], float* sm_act, float* sm_scr,
                                           float* sm_sc, float* sm_sh,
                                           const float* sm_gm, const float* sm_bt,
                                           int m, int g, int tid) {
    float* ssum = sm_scr;
    float* ssq  = sm_scr + 32 * 128;
    __syncthreads();
#pragma unroll
    for (int p = 0; p < 4; ++p) {
        int j0 = 2 * m + 32 * p;
        float s0 = 0.f, q0 = 0.f, s1 = 0.f, q1 = 0.f;
#pragma unroll
        for (int i = 0; i < 8; ++i) {
            float lo, hi;
            unpack2(acc[i][p], lo, hi);
            s0 += lo; q0 += lo * lo;
            s1 += hi; q1 += hi * hi;
        }
        ssum[g * 128 + j0] = s0;     ssq[g * 128 + j0] = q0;
        ssum[g * 128 + j0 + 1] = s1; ssq[g * 128 + j0 + 1] = q1;
    }
    __syncthreads();
    if (tid < 128) {
        float s = 0.f, q = 0.f;
#pragma unroll
        for (int gg = 0; gg < 32; ++gg) {
            s += ssum[gg * 128 + tid];
            q += ssq[gg * 128 + tid];
        }
        float mean = s * (1.0f / 256.0f);
        float var  = q * (1.0f / 256.0f) - mean * mean;
        float inv  = rsqrtf(var + 1e-5f);
        float sc   = sm_gm[tid] * inv;
        sm_sc[tid] = sc;
        sm_sh[tid] = sm_bt[tid] - mean * sc;
    }
    __syncthreads();
#pragma unroll
    for (int p = 0; p < 4; ++p) {
        int j0 = 2 * m + 32 * p;
        float sc0 = sm_sc[j0], sh0 = sm_sh[j0];
        float sc1 = sm_sc[j0 + 1], sh1 = sm_sh[j0 + 1];
#pragma unroll
        for (int i = 0; i < 8; ++i) {
            float lo, hi;
            unpack2(acc[i][p], lo, hi);
            float2 v;
            v.x = fmaxf(fmaf(lo, sc0, sh0), 0.0f);
            v.y = fmaxf(fmaf(hi, sc1, sh1), 0.0f);
            *(float2*)(sm_act + (g * 8 + i) * AP + j0) = v;
        }
    }
}
#endif  // !USE_TC

// ============================= the MLP kernel =============================
__global__ void __launch_bounds__(THREADS, 2) __cluster_dims__(2, 1, 1)
mlp_kernel(const float* __restrict__ s, const float* __restrict__ c,
           const float* __restrict__ sw1, const float* __restrict__ sg1, const float* __restrict__ sbe1,
           const float* __restrict__ sw2, const float* __restrict__ sg2, const float* __restrict__ sbe2,
           const float* __restrict__ sw3, const float* __restrict__ sb3,
           const float* __restrict__ cw1, const float* __restrict__ cg1, const float* __restrict__ cbe1,
           const float* __restrict__ cw2, const float* __restrict__ cg2, const float* __restrict__ cbe2,
           const float* __restrict__ cw3, const float* __restrict__ cb3,
           float* __restrict__ out) {
    extern __shared__ char smc[];
    const int tid = threadIdx.x;
    const bool is_c = ((blockIdx.x >> 1) == 0);
    const int slice = (int)(blockIdx.x >> 1) - 1;

    const float *W1, *W2, *W3, *G1, *G2, *B1, *B2, *B3;
    if (is_c) { W1=cw1; W2=cw2; W3=cw3; G1=cg1; G2=cg2; B1=cbe1; B2=cbe2; B3=cb3; }
    else      { W1=sw1; W2=sw2; W3=sw3; G1=sg1; G2=sg2; B1=sbe1; B2=sbe2; B3=sb3; }

#if USE_TC
    // ======================= cg2 tcgen05 path =======================
    char* sm = smc;
    const uint32_t smb = smem_u32(sm);
    const int wid = tid >> 5;
    const int lane = tid & 31;
    const uint32_t rank = cluster_rank();
    const uint32_t peer = rank ^ 1u;
    const int wrow0 = (int)rank * 64 * 128;   // my W half offset (rows rank*64..)

    if (wid == 0) {
        TCGEN05_ALLOC_CG2(smb + OFF_TMEM, 128);
        TCGEN05_RELINQ_CG2();
    }
    if (tid == 0) {
        MBARRIER_INIT(smb + OFF_MBAR, 1);
        MBARRIER_INIT(smb + OFF_MBAR2, 1);
    }
    __syncthreads();
    uint32_t tmem;
    asm volatile("ld.shared.b32 %0, [%1];" : "=r"(tmem) : "r"(smb + OFF_TMEM));

    // Stage my 128 A-rows: fp32 -> bf16 hi/lo into swizzled tiles
    {
#pragma unroll
        for (int it = 0; it < 4; ++it) {
            int idx = tid + it * THREADS;
            int row = idx >> 4;
            int ch = idx & 15;
            int grow = (int)rank * 128 + row;
            const float* p = is_c ? (c + (size_t)grow * 128 + ch * 8)
                                  : (s + ((size_t)grow * 512 + slice) * 128 + ch * 8);
            float4 a = *(const float4*)p;
            float4 b = *(const float4*)(p + 4);
            float f[8] = {a.x, a.y, a.z, a.w, b.x, b.y, b.z, b.w};
            uint4 H, L;
            split8f(f, H, L);
            uint32_t off = swb(row, ch * 8);
            *(uint4*)(sm + OFF_AHI + off) = H;
            *(uint4*)(sm + OFF_ALO + off) = L;
        }
    }
    // Split my W1 half inline
    split_w_half_sub(sm, W1 + wrow0, tid, THREADS);
    FENCE_PROXY();

    const int rowgrp = wid & 3;
    const int colgrp = wid >> 2;
    const int lrow = rowgrp * 32 + lane;
    const int jbase = colgrp * 32;                          // physical D cols
    // cg2 N=64 permutation: logical output column base {0,64,32,96} by colgrp
    const int jout = ((colgrp & 1) << 6) | ((colgrp >> 1) << 5);
    const bool first_half = (colgrp < 2);                   // D cols 0-63 (chain 1)

    float* scv = (float*)(sm + OFF_SC);
    float* shv = (float*)(sm + OFF_SH);
    float* pst = (float*)(sm + OFF_PST);
    const uint32_t pst_addr = smb + OFF_PST;

    uint32_t d[32];

#pragma unroll 1
    for (int layer = 0; layer < 3; ++layer) {
        // A'/W (and layer 0: mbar init) ready cluster-wide before MMA
        CLUSTER_SYNC();

        if (rank == 0 && wid == 0) {
            if (elect_one_pred()) {
                uint64_t ah = make_desc(smb + OFF_AHI);
                uint64_t al = make_desc(smb + OFF_ALO);
                uint64_t bh = make_desc(smb + OFF_WHI);
                uint64_t bl = make_desc(smb + OFF_WLO);
                // chain 1: W local rows 0-31 (desc +0)  -> D cols 0-63
                // chain 2: W local rows 32-63 (desc +256) -> D cols 64-127
#pragma unroll
                for (int chain = 0; chain < 2; ++chain) {
                    uint32_t dcol = tmem + chain * 64;
                    uint32_t wrow_off = chain * 256;   // 32 rows * 128B / 16
#pragma unroll
                    for (int pass = 0; pass < 3; ++pass) {
                        uint64_t ad = (pass == 2) ? al : ah;
                        uint64_t bd = ((pass == 1) ? bl : bh) + wrow_off;
#pragma unroll
                        for (int ks = 0; ks < 8; ++ks) {
                            uint32_t aoff = ((ks >> 2) << 10) + ((ks & 3) << 1);
                            uint32_t boff = ((ks >> 2) << 9) + ((ks & 3) << 1);
                            mma_bf16_cg2_n64(dcol, ad + aoff, bd + boff,
                                             (pass | ks) ? 1u : 0u);
                        }
                    }
                    TCGEN05_COMMIT_MC2(smb + (chain == 0 ? OFF_MBAR : OFF_MBAR2), 0x3);
                }
            }
        }
        // first-half warps wait chain1 only -> LDTM overlaps chain2 MMA
        MBARRIER_WAIT_PARITY(smb + (first_half ? OFF_MBAR : OFF_MBAR2), layer & 1);
        TCGEN05_FENCE_AFTER();

        TCGEN05_LD_X32(d, tmem + jbase);

        // next-layer W split: only second-half warps (they passed mbar2 =>
        // ALL MMAs done; commit tracks all prior MMAs). Overlaps chain-1
        // warps' butterflies.
        if (layer < 2 && !first_half) {
            split_w_half_sub(sm, ((layer == 0 ? W2 : W3) + wrow0), tid - 256, 256);
        }
        TCGEN05_WAIT_LD();
        TCGEN05_FENCE_BEFORE();

        if (layer < 2) {
            // ---- per-warp (sum, sumsq) over 32 rows via butterfly transpose ----
            {
                float s16[16];
#pragma unroll
                for (int i = 0; i < 16; ++i) {
                    float dlo = __uint_as_float(d[i]);
                    float dhi = __uint_as_float(d[16 + i]);
                    bool up = (lane & 16);
                    float dk = up ? dhi : dlo;
                    float ds = up ? dlo : dhi;
                    s16[i] = dk + __shfl_xor_sync(0xFFFFFFFFu, ds, 16);
                }
                float s8[8];
#pragma unroll
                for (int i = 0; i < 8; ++i) {
                    bool up = (lane & 8);
                    float k = up ? s16[8 + i] : s16[i];
                    float sn = up ? s16[i] : s16[8 + i];
                    s8[i] = k + __shfl_xor_sync(0xFFFFFFFFu, sn, 8);
                }
                float s4[4];
#pragma unroll
                for (int i = 0; i < 4; ++i) {
                    bool up = (lane & 4);
                    float k = up ? s8[4 + i] : s8[i];
                    float sn = up ? s8[i] : s8[4 + i];
                    s4[i] = k + __shfl_xor_sync(0xFFFFFFFFu, sn, 4);
                }
                float s2[2];
#pragma unroll
                for (int i = 0; i < 2; ++i) {
                    bool up = (lane & 2);
                    float k = up ? s4[2 + i] : s4[i];
                    float sn = up ? s4[i] : s4[2 + i];
                    s2[i] = k + __shfl_xor_sync(0xFFFFFFFFu, sn, 2);
                }
                {
                    bool up = (lane & 1);
                    float k = up ? s2[1] : s2[0];
                    float sn = up ? s2[0] : s2[1];
                    float s1 = k + __shfl_xor_sync(0xFFFFFFFFu, sn, 1);
                    pst[rowgrp * 128 + jout + lane] = s1;   // logical column index
                }
                float q16[16];
#pragma unroll
                for (int i = 0; i < 16; ++i) {
                    float dlo = __uint_as_float(d[i]);
                    float dhi = __uint_as_float(d[16 + i]);
                    bool up = (lane & 16);
                    float dk = up ? dhi : dlo;
                    float ds = up ? dlo : dhi;
                    float rv = __shfl_xor_sync(0xFFFFFFFFu, ds, 16);
                    q16[i] = fmaf(dk, dk, rv * rv);
                }
                float q8[8];
#pragma unroll
                for (int i = 0; i < 8; ++i) {
                    bool up = (lane & 8);
                    float k = up ? q16[8 + i] : q16[i];
                    float sn = up ? q16[i] : q16[8 + i];
                    q8[i] = k + __shfl_xor_sync(0xFFFFFFFFu, sn, 8);
                }
                float q4[4];
#pragma unroll
                for (int i = 0; i < 4; ++i) {
                    bool up = (lane & 4);
                    float k = up ? q8[4 + i] : q8[i];
                    float sn = up ? q8[i] : q8[4 + i];
                    q4[i] = k + __shfl_xor_sync(0xFFFFFFFFu, sn, 4);
                }
                float q2[2];
#pragma unroll
                for (int i = 0; i < 2; ++i) {
                    bool up = (lane & 2);
                    float k = up ? q4[2 + i] : q4[i];
                    float sn = up ? q4[i] : q4[2 + i];
                    q2[i] = k + __shfl_xor_sync(0xFFFFFFFFu, sn, 2);
                }
                {
                    bool up = (lane & 1);
                    float k = up ? q2[1] : q2[0];
                    float sn = up ? q2[0] : q2[1];
                    float q1 = k + __shfl_xor_sync(0xFFFFFFFFu, sn, 1);
                    pst[512 + rowgrp * 128 + jout + lane] = q1;
                }
            }
            // both CTAs' partials visible cluster-wide
            CLUSTER_SYNC();

            if (tid < 128) {
                float ss = pst[tid] + pst[128 + tid] + pst[256 + tid] + pst[384 + tid];
                float qq = pst[512 + tid] + pst[640 + tid] + pst[768 + tid] + pst[896 + tid];
#pragma unroll
                for (int k = 0; k < 4; ++k) {
                    ss += ld_dsmem_f32(pst_addr + (uint32_t)(k * 128 + tid) * 4u, peer);
                    qq += ld_dsmem_f32(pst_addr + (uint32_t)(512 + k * 128 + tid) * 4u, peer);
                }
                float mean = ss * (1.0f / 256.0f);
                float var = qq * (1.0f / 256.0f) - mean * mean;
                float inv = rsqrtf(var + 1e-5f);
                float gm = __ldg((layer ? G2 : G1) + tid);
                float bt = __ldg((layer ? B2 : B1) + tid);
                float scl = gm * inv;
                scv[tid] = scl;
                shv[tid] = bt - mean * scl;   // linear bias cancels in BN
            }
            __syncthreads();

            // normalize + ReLU, split to bf16 hi/lo, store next A at LOGICAL cols
            {
#pragma unroll
                for (int c8 = 0; c8 < 4; ++c8) {
                    int j0 = jout + c8 * 8;
                    float f[8];
#pragma unroll
                    for (int i = 0; i < 8; ++i) {
                        f[i] = fmaxf(fmaf(__uint_as_float(d[c8 * 8 + i]), scv[j0 + i], shv[j0 + i]), 0.f);
                    }
                    uint4 H, L;
                    split8f(f, H, L);
                    uint32_t off = swb(lrow, j0);
                    *(uint4*)(sm + OFF_AHI + off) = H;
                    *(uint4*)(sm + OFF_ALO + off) = L;
                }
            }
            FENCE_PROXY();
            // next iteration's CLUSTER_SYNC orders A'/W for the next MMA
        }
    }

    // ---- layer-3 epilogue: +b3, gate, write (logical columns jout..jout+31) ----
    const int grow = (int)rank * 128 + lrow;
    const int q0 = jout >> 2;
    if (is_c) {
#pragma unroll
        for (int q = 0; q < 8; ++q) {
            float4 bb = __ldg((const float4*)B3 + q0 + q);
            float4 v;
            v.x = __uint_as_float(d[4 * q + 0]) + bb.x;
            v.y = __uint_as_float(d[4 * q + 1]) + bb.y;
            v.z = __uint_as_float(d[4 * q + 2]) + bb.z;
            v.w = __uint_as_float(d[4 * q + 3]) + bb.w;
            g_c_out[grow * 32 + q0 + q] = v;
        }
        __threadfence();
        CLUSTER_SYNC();   // both c-CTAs' writes done
        if (rank == 0 && tid == 0) atomicExch(&g_flag, 1);
    } else {
        if (tid == 0) {
            while (atomicAdd(&g_flag, 0) == 0) { }
            __threadfence();
        }
        __syncthreads();
        float* op = out + ((size_t)grow * 512 + slice) * 128 + jout;
#pragma unroll
        for (int q = 0; q < 8; ++q) {
            float4 bb = __ldg((const float4*)B3 + q0 + q);
            float4 cv = __ldcg(&g_c_out[grow * 32 + q0 + q]);
            float4 v;
            v.x = (__uint_as_float(d[4 * q + 0]) + bb.x) * cv.x;
            v.y = (__uint_as_float(d[4 * q + 1]) + bb.y) * cv.y;
            v.z = (__uint_as_float(d[4 * q + 2]) + bb.z) * cv.z;
            v.w = (__uint_as_float(d[4 * q + 3]) + bb.w) * cv.w;
            ((float4*)op)[q] = v;
        }
    }

    CLUSTER_SYNC();
    if (tid == 0) {
        MBARRIER_INVAL(smb + OFF_MBAR);
        MBARRIER_INVAL(smb + OFF_MBAR2);
    }
    __syncthreads();
    if (wid == 0) TCGEN05_DEALLOC_CG2(tmem, 128);

#else
    // ============== FFMA2 fallback (compile-only; sm_103a SASS always runs) ==============
    if (blockIdx.x & 1) return;
    float* smf = (float*)smc;
    float* sm_act = smf;
    float* sm_wt  = smf + SM_ACT_F;
    float* sm_sc  = sm_wt + SM_WT_F;
    float* sm_sh  = sm_sc + 128;
    float* sm_gm  = sm_sh + 128;
    float* sm_bt  = sm_gm + 128;
    const int m = tid & 15;
    const int g = tid >> 4;

    {
        const float* src = is_c ? c : (s + (size_t)slice * 128);
        const size_t rstride = is_c ? (size_t)128 : (size_t)512 * 128;
        for (int idx = tid; idx < 256 * 32; idx += THREADS) {
            int r = idx >> 5;
            int kc = (idx & 31) << 2;
            float4 v = *(const float4*)(src + (size_t)r * rstride + kc);
            *(float4*)(sm_act + r * AP + kc) = v;
        }
    }
    load_wt(sm_wt, W1, tid);
    if (tid < 128) { sm_gm[tid] = G1[tid]; sm_bt[tid] = B1[tid]; }
    __syncthreads();

    u64 acc[8][4];
    fb_gemm(acc, sm_act, sm_wt, m, g);
    fb_bn_relu(acc, sm_act, sm_wt, sm_sc, sm_sh, sm_gm, sm_bt, m, g, tid);
    load_wt(sm_wt, W2, tid);
    if (tid < 128) { sm_gm[tid] = G2[tid]; sm_bt[tid] = B2[tid]; }
    __syncthreads();

    fb_gemm(acc, sm_act, sm_wt, m, g);
    fb_bn_relu(acc, sm_act, sm_wt, sm_sc, sm_sh, sm_gm, sm_bt, m, g, tid);
    load_wt(sm_wt, W3, tid);
    if (tid < 128) sm_bt[tid] = B3[tid];
    __syncthreads();

    fb_gemm(acc, sm_act, sm_wt, m, g);

    float* gco = (float*)g_c_out;
    if (is_c) {
#pragma unroll
        for (int p = 0; p < 4; ++p) {
            int j0 = 2 * m + 32 * p;
            float bb0 = sm_bt[j0], bb1 = sm_bt[j0 + 1];
#pragma unroll
            for (int i = 0; i < 8; ++i) {
                float lo, hi;
                unpack2(acc[i][p], lo, hi);
                float2 v; v.x = lo + bb0; v.y = hi + bb1;
                *(float2*)&gco[(g * 8 + i) * 128 + j0] = v;
            }
        }
        __threadfence();
        __syncthreads();
        if (tid == 0) atomicExch(&g_flag, 1);
    } else {
        if (tid == 0) {
            while (atomicAdd(&g_flag, 0) == 0) { }
            __threadfence();
        }
        __syncthreads();
#pragma unroll
        for (int p = 0; p < 4; ++p) {
            int j0 = 2 * m + 32 * p;
            float bb0 = sm_bt[j0], bb1 = sm_bt[j0 + 1];
#pragma unroll
            for (int i = 0; i < 8; ++i) {
                int r = g * 8 + i;
                float lo, hi;
                unpack2(acc[i][p], lo, hi);
                float2 cv = __ldcg((const float2*)&gco[r * 128 + j0]);
                float2 v;
                v.x = (lo + bb0) * cv.x;
                v.y = (hi + bb1) * cv.y;
                *(float2*)(out + ((size_t)r * 512 + slice) * 128 + j0) = v;
            }
        }
    }
#endif
}

// ---- Max-pool stage 1: grid 1024 = b(256) x seg(4, 128 slices each) ----
__global__ void __launch_bounds__(256, 8)
partial_max(const float* __restrict__ so) {
    __shared__ float4 red[8][32];
    int b = blockIdx.x >> 2;
    int seg = blockIdx.x & 3;
    int c4 = threadIdx.x & 31;
    int sub = threadIdx.x >> 5;
    const float4* p = (const float4*)(so + ((size_t)b * 512 + seg * 128 + sub * 16) * 128) + c4;
    float4 mx = make_float4(-3.4e38f, -3.4e38f, -3.4e38f, -3.4e38f);
#pragma unroll 16
    for (int i = 0; i < 16; ++i) {
        float4 v = p[(size_t)i * 32];
        mx.x = fmaxf(mx.x, v.x); mx.y = fmaxf(mx.y, v.y);
        mx.z = fmaxf(mx.z, v.z); mx.w = fmaxf(mx.w, v.w);
    }
    red[sub][c4] = mx;
    __syncthreads();
    if (threadIdx.x < 32) {
        float4 r = red[0][c4];
#pragma unroll
        for (int ss = 1; ss < 8; ++ss) {
            float4 v = red[ss][c4];
            r.x = fmaxf(r.x, v.x); r.y = fmaxf(r.y, v.y);
            r.z = fmaxf(r.z, v.z); r.w = fmaxf(r.w, v.w);
        }
        g_part[(size_t)blockIdx.x * 32 + c4] = r;
    }
}

// ---- Max-pool stage 2; also resets flag for graph replay ----
__global__ void final_max(float* __restrict__ agg) {
    if (blockIdx.x == 0 && threadIdx.x == 0) g_flag = 0;
    int idx = blockIdx.x * 256 + threadIdx.x;
    int b = idx >> 5;
    int c4 = idx & 31;
    float4 r = g_part[(size_t)(b * 4) * 32 + c4];
#pragma unroll
    for (int seg = 1; seg < 4; ++seg) {
        float4 v = g_part[(size_t)(b * 4 + seg) * 32 + c4];
        r.x = fmaxf(r.x, v.x); r.y = fmaxf(r.y, v.y);
        r.z = fmaxf(r.z, v.z); r.w = fmaxf(r.w, v.w);
    }
    ((float4*)agg)[idx] = r;
}

extern "C" void kernel_launch(void* const* d_in, const int* in_sizes, int n_in,
                              void* d_out, int out_size) {
    const float* s    = (const float*)d_in[0];
    const float* c    = (const float*)d_in[1];
    const float* sw1  = (const float*)d_in[2];
    const float* sg1  = (const float*)d_in[4];
    const float* sbe1 = (const float*)d_in[5];
    const float* sw2  = (const float*)d_in[6];
    const float* sg2  = (const float*)d_in[8];
    const float* sbe2 = (const float*)d_in[9];
    const float* sw3  = (const float*)d_in[10];
    const float* sb3  = (const float*)d_in[11];
    const float* cw1  = (const float*)d_in[12];
    const float* cg1  = (const float*)d_in[14];
    const float* cbe1 = (const float*)d_in[15];
    const float* cw2  = (const float*)d_in[16];
    const float* cg2  = (const float*)d_in[18];
    const float* cbe2 = (const float*)d_in[19];
    const float* cw3  = (const float*)d_in[20];
    const float* cb3  = (const float*)d_in[21];
    float* out = (float*)d_out;

    cudaFuncSetAttribute(mlp_kernel, cudaFuncAttributeMaxDynamicSharedMemorySize, SM_TC_BYTES);

    // 513 clusters x 2 CTAs: cluster 0 = c-path, clusters 1..512 = slices
    mlp_kernel<<<1026, THREADS, SM_TC_BYTES>>>(s, c,
                                               sw1, sg1, sbe1, sw2, sg2, sbe2, sw3, sb3,
                                               cw1, cg1, cbe1, cw2, cg2, cbe2, cw3, cb3,
                                               out);

    float* agg = out + ((size_t)out_size - 256 * 128);
    partial_max<<<1024, 256>>>(out);
    final_max<<<32, 256>>>(agg);
}

// round 17
// speedup vs baseline: 1.1357x; 1.0578x over previous
#include <cuda_runtime.h>
#include <cuda_bf16.h>
#include <cstdint>

// CGBlock: per-slice 3-layer MLP (Linear->BN->ReLU x2 ->Linear), context gate,
// max-pool. B=256, S=512, D=128 fp32.
// cta_group::2 bf16x3-split SS MMA (M=256 per 2-CTA cluster), 2 CTAs/SM.
// R17 = R10 (138us baseline) + (1) BN-partials PUSH model (remote DSMEM stores
// by producers; combine reads local only) + (2) single-launch fused max-pool
// (1024 partial blocks + 32 spinning finalizer blocks).

#define THREADS 512

#if defined(__CUDA_ARCH__) && (defined(__CUDA_ARCH_FEAT_SM103_ALL) || defined(__CUDA_ARCH_FEAT_SM100_ALL) || defined(__CUDA_ARCH_FEAT_SM101_ALL))
#define USE_TC 1
#else
#define USE_TC 0
#endif

// ---------------- shared device state ----------------
__device__ float4 g_c_out[256 * 32];
__device__ int g_flag = 0;
__device__ int g_done = 0;
__device__ int g_fin = 0;
__device__ float4 g_part[1024 * 32];

// ---------------- TC-path SMEM layout (bytes) ----------------
#define OFF_TMEM 0
#define OFF_MBAR 8
#define OFF_AHI  1024      // A_hi: 128r x 128k bf16 blocked-SW128 = 32768
#define OFF_ALO  33792     // A_lo: 32768
#define OFF_WHI  66560     // W_hi half: 64r x 128k = 16384
#define OFF_WLO  82944     // W_lo half: 16384
#define OFF_SC   99328     // BN scale f32[128]
#define OFF_SH   99840     // BN shift f32[128]
#define OFF_PST  100352    // f32[2048]: [cta][4 rowgrp][128] sums, then sumsq
#define SM_TC_BYTES 108544

// idesc kind::f16 cg2: c=F32, a=BF16, b=BF16, N=128, M=256
#define IDESC2 0x10200490u

typedef unsigned long long u64;

__device__ __forceinline__ uint32_t smem_u32(const void* p) {
    uint32_t a;
    asm("{ .reg .u64 t; cvta.to.shared.u64 t, %1; cvt.u32.u64 %0, t; }" : "=r"(a) : "l"(p));
    return a;
}

// Blocked SW128 addr, 128-row bf16 tile (16 atom-rows x 2 atom-cols).
__device__ __forceinline__ uint32_t swb(int rl, int j0) {
    uint32_t off = (uint32_t)((((rl >> 3) + ((j0 >> 6) << 4)) << 10) + ((rl & 7) << 7) + ((j0 & 63) << 1));
    return off ^ ((off >> 3) & 0x70);
}
// Blocked SW128 addr, 64-row bf16 tile (8 atom-rows x 2 atom-cols).
__device__ __forceinline__ uint32_t swb64(int rl, int j0) {
    uint32_t off = (uint32_t)((((rl >> 3) + ((j0 >> 6) << 3)) << 10) + ((rl & 7) << 7) + ((j0 & 63) << 1));
    return off ^ ((off >> 3) & 0x70);
}

// Fast split: hi = bf16-truncate (PRMT pack), lo = rn_bf16(x - hi).
__device__ __forceinline__ void split_pair(float x, float y, uint32_t& h, uint32_t& l) {
    uint32_t bx = __float_as_uint(x), by = __float_as_uint(y);
    asm("prmt.b32 %0, %1, %2, 0x7632;" : "=r"(h) : "r"(bx), "r"(by));
    float lx = x - __uint_as_float(bx & 0xFFFF0000u);
    float ly = y - __uint_as_float(by & 0xFFFF0000u);
    asm("cvt.rn.bf16x2.f32 %0, %1, %2;" : "=r"(l) : "f"(ly), "f"(lx));
}
__device__ __forceinline__ void split8f(const float* f, uint4& h, uint4& l) {
    uint32_t hh[4], ll[4];
#pragma unroll
    for (int i = 0; i < 4; ++i) split_pair(f[2 * i], f[2 * i + 1], hh[i], ll[i]);
    h = make_uint4(hh[0], hh[1], hh[2], hh[3]);
    l = make_uint4(ll[0], ll[1], ll[2], ll[3]);
}

#if USE_TC
// ---------------- tcgen05 / cluster PTX (arch-specific passes only) ----------------
__device__ __forceinline__ uint32_t elect_one_pred() {
    uint32_t pred;
    asm volatile("{\n\t.reg .pred p;\n\telect.sync _|p, 0xFFFFFFFF;\n\tselp.b32 %0, 1, 0, p;\n\t}"
                 : "=r"(pred));
    return pred;
}
__device__ __forceinline__ uint32_t cluster_rank() {
    uint32_t r;
    asm("mov.u32 %0, %%cluster_ctarank;" : "=r"(r));
    return r;
}
#define CLUSTER_SYNC() do { \
    asm volatile("barrier.cluster.arrive.aligned;" ::: "memory"); \
    asm volatile("barrier.cluster.wait.aligned;" ::: "memory"); \
} while (0)
// Fire-and-forget push of a f32 into the peer CTA's smem (DSMEM store).
__device__ __forceinline__ void st_dsmem_f32(uint32_t addr, uint32_t rankv, float v) {
    uint32_t ra;
    asm("mapa.shared::cluster.u32 %0, %1, %2;" : "=r"(ra) : "r"(addr), "r"(rankv));
    asm volatile("st.shared::cluster.f32 [%0], %1;" :: "r"(ra), "f"(v) : "memory");
}
#define TCGEN05_ALLOC_CG2(a, n) \
    asm volatile("tcgen05.alloc.cta_group::2.sync.aligned.shared::cta.b32 [%0], %1;" \
                 :: "r"((uint32_t)(a)), "r"((uint32_t)(n)) : "memory")
#define TCGEN05_DEALLOC_CG2(t, n) \
    asm volatile("tcgen05.dealloc.cta_group::2.sync.aligned.b32 %0, %1;" :: "r"(t), "r"((uint32_t)(n)))
#define TCGEN05_RELINQ_CG2() \
    asm volatile("tcgen05.relinquish_alloc_permit.cta_group::2.sync.aligned;")
#define TCGEN05_WAIT_LD()  asm volatile("tcgen05.wait::ld.sync.aligned;" ::: "memory")
#define TCGEN05_FENCE_BEFORE() asm volatile("tcgen05.fence::before_thread_sync;" ::: "memory")
#define TCGEN05_FENCE_AFTER()  asm volatile("tcgen05.fence::after_thread_sync;" ::: "memory")
#define FENCE_PROXY() asm volatile("fence.proxy.async.shared::cta;" ::: "memory")
#define MBARRIER_INIT(m, c) \
    asm volatile("mbarrier.init.shared.b64 [%0], %1;" :: "r"((uint32_t)(m)), "r"((uint32_t)(c)) : "memory")
#define MBARRIER_INVAL(m) \
    asm volatile("mbarrier.inval.shared.b64 [%0];" :: "r"((uint32_t)(m)) : "memory")
#define MBARRIER_WAIT_PARITY(mb, ph) do { \
    uint32_t _m = (uint32_t)(mb); uint32_t _p = (uint32_t)(ph); uint32_t _d; \
    asm volatile("{\n\t.reg .pred p;\n\t" \
        "mbarrier.try_wait.parity.acquire.cta.shared::cta.b64 p, [%1], %2;\n\t" \
        "selp.b32 %0, 1, 0, p;\n\t}" : "=r"(_d) : "r"(_m), "r"(_p) : "memory"); \
    if (!_d) { \
        asm volatile("{\n\t.reg .pred P1;\n\t" \
            "WAIT_LOOP_%=:\n\t" \
            "mbarrier.try_wait.parity.acquire.cta.shared::cta.b64 P1, [%0], %1, 0x989680;\n\t" \
            "@P1 bra.uni WAIT_DONE_%=;\n\t" \
            "bra.uni WAIT_LOOP_%=;\n\t" \
            "WAIT_DONE_%=:\n\t}" :: "r"(_m), "r"(_p) : "memory"); \
    } \
} while (0)
#define TCGEN05_LD_X32(r, a) \
    asm volatile("tcgen05.ld.sync.aligned.32x32b.x32.b32 " \
        "{%0, %1, %2, %3, %4, %5, %6, %7, %8, %9, %10, %11, %12, %13, %14, %15, " \
        " %16, %17, %18, %19, %20, %21, %22, %23, %24, %25, %26, %27, %28, %29, %30, %31}, [%32];" \
        : "=r"((r)[0]),  "=r"((r)[1]),  "=r"((r)[2]),  "=r"((r)[3]), \
          "=r"((r)[4]),  "=r"((r)[5]),  "=r"((r)[6]),  "=r"((r)[7]), \
          "=r"((r)[8]),  "=r"((r)[9]),  "=r"((r)[10]), "=r"((r)[11]), \
          "=r"((r)[12]), "=r"((r)[13]), "=r"((r)[14]), "=r"((r)[15]), \
          "=r"((r)[16]), "=r"((r)[17]), "=r"((r)[18]), "=r"((r)[19]), \
          "=r"((r)[20]), "=r"((r)[21]), "=r"((r)[22]), "=r"((r)[23]), \
          "=r"((r)[24]), "=r"((r)[25]), "=r"((r)[26]), "=r"((r)[27]), \
          "=r"((r)[28]), "=r"((r)[29]), "=r"((r)[30]), "=r"((r)[31]) \
        : "r"(a))

// cg2 bf16 SS MMA (kind::f16; 8-reg disable-output-lane = all enabled)
__device__ __forceinline__ void mma_bf16_cg2(uint32_t d, uint64_t a, uint64_t b, uint32_t en) {
    asm volatile(
        "{\n\t.reg .pred p;\n\tsetp.ne.u32 p, %5, 0;\n\t"
        "tcgen05.mma.cta_group::2.kind::f16 [%0], %1, %2, %3, "
        "{%4, %4, %4, %4, %4, %4, %4, %4}, p;\n\t}"
        :: "r"(d), "l"(a), "l"(b), "r"(IDESC2), "r"(0u), "r"(en) : "memory");
}
#define TCGEN05_COMMIT_MC2(mbar, mask) \
    asm volatile("tcgen05.commit.cta_group::2.mbarrier::arrive::one.shared::cluster.multicast::cluster.b64 [%0], %1;" \
                 :: "r"((uint32_t)(mbar)), "h"((uint16_t)(mask)) : "memory")

__device__ __forceinline__ uint64_t make_desc(uint32_t addr) {
    const uint64_t base = (uint64_t(2) << 61) | (uint64_t(1) << 46) |
                          (uint64_t(64) << 32) | (uint64_t(1) << 16);
    return base | ((uint64_t)(addr >> 4) & 0x3FFF);
}

// Inline split of my 64-row W half (raw fp32, row-major) into smem hi/lo tiles.
__device__ __forceinline__ void split_w_half(char* sm, const float* __restrict__ wsrc, int tid) {
#pragma unroll
    for (int it = 0; it < 2; ++it) {
        int idx = tid + it * THREADS;      // 0..1023 = 64 rows x 16 chunks
        int row = idx >> 4;
        int ch = idx & 15;
        const float* p = wsrc + row * 128 + ch * 8;
        float4 a = *(const float4*)p;
        float4 b = *(const float4*)(p + 4);
        float f[8] = {a.x, a.y, a.z, a.w, b.x, b.y, b.z, b.w};
        uint4 H, L;
        split8f(f, H, L);
        uint32_t off = swb64(row, ch * 8);
        *(uint4*)(sm + OFF_WHI + off) = H;
        *(uint4*)(sm + OFF_WLO + off) = L;
    }
}
#endif  // USE_TC

// ---------------- fallback helpers (compile-only on non-arch passes) ----------------
#if !USE_TC
#define AP 132
#define WP 130
#define SM_ACT_F (256 * AP)
#define SM_WT_F  (128 * WP)
__device__ __forceinline__ u64 pack2(float x) {
    u64 r;
    unsigned int xi = __float_as_uint(x);
    asm("mov.b64 %0, {%1, %1};" : "=l"(r) : "r"(xi));
    return r;
}
__device__ __forceinline__ void fma2(u64& d, u64 a, u64 b) {
    asm("fma.rn.f32x2 %0, %1, %2, %0;" : "+l"(d) : "l"(a), "l"(b));
}
__device__ __forceinline__ void unpack2(u64 v, float& lo, float& hi) {
    unsigned int a, b;
    asm("mov.b64 {%0, %1}, %2;" : "=r"(a), "=r"(b) : "l"(v));
    lo = __uint_as_float(a);
    hi = __uint_as_float(b);
}
__device__ __forceinline__ void load_wt(float* sm_wt, const float* __restrict__ w, int tid) {
    for (int idx = tid; idx < 128 * 32; idx += THREADS) {
        int j = idx >> 5;
        int kc = (idx & 31) << 2;
        float4 v = *(const float4*)(w + j * 128 + kc);
        sm_wt[(kc + 0) * WP + j] = v.x;
        sm_wt[(kc + 1) * WP + j] = v.y;
        sm_wt[(kc + 2) * WP + j] = v.z;
        sm_wt[(kc + 3) * WP + j] = v.w;
    }
}
__device__ __forceinline__ void fb_gemm(u64 (&acc)[8][4], const float* sm_act,
                                        const float* sm_wt, int m, int g) {
#pragma unroll
    for (int i = 0; i < 8; ++i)
#pragma unroll
        for (int p = 0; p < 4; ++p) acc[i][p] = 0ULL;
    const float* a0 = sm_act + (g * 8) * AP;
#pragma unroll 2
    for (int k = 0; k < 128; ++k) {
        const float* wk = sm_wt + k * WP + 2 * m;
        u64 b0 = *(const u64*)(wk);
        u64 b1 = *(const u64*)(wk + 32);
        u64 b2 = *(const u64*)(wk + 64);
        u64 b3 = *(const u64*)(wk + 96);
#pragma unroll
        for (int i = 0; i < 8; ++i) {
            u64 a2 = pack2(a0[i * AP + k]);
            fma2(acc[i][0], a2, b0);
            fma2(acc[i][1], a2, b1);
            fma2(acc[i][2], a2, b2);
            fma2(acc[i][3], a2, b3);
        }
    }
}
__device__ __forceinline__ void fb_bn_relu(u64 (&acc)[8][4], float* sm_act, float* sm_scr,
                                           float* sm_sc, float* sm_sh,
                                           const float* sm_gm, const float* sm_bt,
                                           int m, int g, int tid) {
    float* ssum = sm_scr;
    float* ssq  = sm_scr + 32 * 128;
    __syncthreads();
#pragma unroll
    for (int p = 0; p < 4; ++p) {
        int j0 = 2 * m + 32 * p;
        float s0 = 0.f, q0 = 0.f, s1 = 0.f, q1 = 0.f;
#pragma unroll
        for (int i = 0; i < 8; ++i) {
            float lo, hi;
            unpack2(acc[i][p], lo, hi);
            s0 += lo; q0 += lo * lo;
            s1 += hi; q1 += hi * hi;
        }
        ssum[g * 128 + j0] = s0;     ssq[g * 128 + j0] = q0;
        ssum[g * 128 + j0 + 1] = s1; ssq[g * 128 + j0 + 1] = q1;
    }
    __syncthreads();
    if (tid < 128) {
        float s = 0.f, q = 0.f;
#pragma unroll
        for (int gg = 0; gg < 32; ++gg) {
            s += ssum[gg * 128 + tid];
            q += ssq[gg * 128 + tid];
        }
        float mean = s * (1.0f / 256.0f);
        float var  = q * (1.0f / 256.0f) - mean * mean;
        float inv  = rsqrtf(var + 1e-5f);
        float sc   = sm_gm[tid] * inv;
        sm_sc[tid] = sc;
        sm_sh[tid] = sm_bt[tid] - mean * sc;
    }
    __syncthreads();
#pragma unroll
    for (int p = 0; p < 4; ++p) {
        int j0 = 2 * m + 32 * p;
        float sc0 = sm_sc[j0], sh0 = sm_sh[j0];
        float sc1 = sm_sc[j0 + 1], sh1 = sm_sh[j0 + 1];
#pragma unroll
        for (int i = 0; i < 8; ++i) {
            float lo, hi;
            unpack2(acc[i][p], lo, hi);
            float2 v;
            v.x = fmaxf(fmaf(lo, sc0, sh0), 0.0f);
            v.y = fmaxf(fmaf(hi, sc1, sh1), 0.0f);
            *(float2*)(sm_act + (g * 8 + i) * AP + j0) = v;
        }
    }
}
#endif  // !USE_TC

// ============================= the MLP kernel =============================
__global__ void __launch_bounds__(THREADS, 2) __cluster_dims__(2, 1, 1)
mlp_kernel(const float* __restrict__ s, const float* __restrict__ c,
           const float* __restrict__ sw1, const float* __restrict__ sg1, const float* __restrict__ sbe1,
           const float* __restrict__ sw2, const float* __restrict__ sg2, const float* __restrict__ sbe2,
           const float* __restrict__ sw3, const float* __restrict__ sb3,
           const float* __restrict__ cw1, const float* __restrict__ cg1, const float* __restrict__ cbe1,
           const float* __restrict__ cw2, const float* __restrict__ cg2, const float* __restrict__ cbe2,
           const float* __restrict__ cw3, const float* __restrict__ cb3,
           float* __restrict__ out) {
    extern __shared__ char smc[];
    const int tid = threadIdx.x;
    const bool is_c = ((blockIdx.x >> 1) == 0);
    const int slice = (int)(blockIdx.x >> 1) - 1;

    const float *W1, *W2, *W3, *G1, *G2, *B1, *B2, *B3;
    if (is_c) { W1=cw1; W2=cw2; W3=cw3; G1=cg1; G2=cg2; B1=cbe1; B2=cbe2; B3=cb3; }
    else      { W1=sw1; W2=sw2; W3=sw3; G1=sg1; G2=sg2; B1=sbe1; B2=sbe2; B3=sb3; }

#if USE_TC
    // ======================= cg2 tcgen05 path =======================
    char* sm = smc;
    const uint32_t smb = smem_u32(sm);
    const int wid = tid >> 5;
    const int lane = tid & 31;
    const uint32_t rank = cluster_rank();
    const uint32_t peer = rank ^ 1u;
    const int wrow0 = (int)rank * 64 * 128;   // my W half offset (rows rank*64..)

    if (wid == 0) {
        TCGEN05_ALLOC_CG2(smb + OFF_TMEM, 128);
        TCGEN05_RELINQ_CG2();
    }
    if (tid == 0) MBARRIER_INIT(smb + OFF_MBAR, 1);
    __syncthreads();
    uint32_t tmem;
    asm volatile("ld.shared.b32 %0, [%1];" : "=r"(tmem) : "r"(smb + OFF_TMEM));

    // Stage my 128 A-rows: fp32 -> bf16 hi/lo into swizzled tiles
    {
#pragma unroll
        for (int it = 0; it < 4; ++it) {
            int idx = tid + it * THREADS;
            int row = idx >> 4;
            int ch = idx & 15;
            int grow = (int)rank * 128 + row;
            const float* p = is_c ? (c + (size_t)grow * 128 + ch * 8)
                                  : (s + ((size_t)grow * 512 + slice) * 128 + ch * 8);
            float4 a = *(const float4*)p;
            float4 b = *(const float4*)(p + 4);
            float f[8] = {a.x, a.y, a.z, a.w, b.x, b.y, b.z, b.w};
            uint4 H, L;
            split8f(f, H, L);
            uint32_t off = swb(row, ch * 8);
            *(uint4*)(sm + OFF_AHI + off) = H;
            *(uint4*)(sm + OFF_ALO + off) = L;
        }
    }
    // Split my W1 half inline (raw fp32 from gmem/L2 -> swizzled bf16 hi/lo)
    split_w_half(sm, W1 + wrow0, tid);
    FENCE_PROXY();

    const int rowgrp = wid & 3;
    const int colgrp = wid >> 2;
    const int lrow = rowgrp * 32 + lane;
    const int jbase = colgrp * 32;

    float* scv = (float*)(sm + OFF_SC);
    float* shv = (float*)(sm + OFF_SH);
    float* pst = (float*)(sm + OFF_PST);
    const uint32_t pst_addr = smb + OFF_PST;

    uint32_t d[32];

#pragma unroll 1
    for (int layer = 0; layer < 3; ++layer) {
        // A'/W (and layer 0: mbar init) ready cluster-wide before MMA
        CLUSTER_SYNC();

        if (rank == 0 && wid == 0) {
            if (elect_one_pred()) {
                uint64_t ah = make_desc(smb + OFF_AHI);
                uint64_t al = make_desc(smb + OFF_ALO);
                uint64_t bh = make_desc(smb + OFF_WHI);
                uint64_t bl = make_desc(smb + OFF_WLO);
#pragma unroll
                for (int pass = 0; pass < 3; ++pass) {
                    uint64_t ad = (pass == 2) ? al : ah;
                    uint64_t bd = (pass == 1) ? bl : bh;
#pragma unroll
                    for (int ks = 0; ks < 8; ++ks) {
                        uint32_t aoff = ((ks >> 2) << 10) + ((ks & 3) << 1);
                        uint32_t boff = ((ks >> 2) << 9) + ((ks & 3) << 1);
                        mma_bf16_cg2(tmem, ad + aoff, bd + boff, (pass | ks) ? 1u : 0u);
                    }
                }
                TCGEN05_COMMIT_MC2(smb + OFF_MBAR, 0x3);
            }
        }
        MBARRIER_WAIT_PARITY(smb + OFF_MBAR, layer & 1);
        TCGEN05_FENCE_AFTER();

        TCGEN05_LD_X32(d, tmem + jbase);

        // split next-layer W half (MMA chain fully done -> W region free)
        if (layer < 2) {
            split_w_half(sm, (layer == 0 ? W2 : W3) + wrow0, tid);
        }
        TCGEN05_WAIT_LD();
        TCGEN05_FENCE_BEFORE();

        if (layer < 2) {
            // ---- per-warp (sum, sumsq) over 32 rows via butterfly transpose;
            //      PUSH partials to both local and peer pst (rank-disjoint slots)
            {
                const uint32_t slot_s = (uint32_t)((int)rank * 512 + rowgrp * 128 + jbase + lane);
                const uint32_t slot_q = 1024u + slot_s;
                float s16[16];
#pragma unroll
                for (int i = 0; i < 16; ++i) {
                    float dlo = __uint_as_float(d[i]);
                    float dhi = __uint_as_float(d[16 + i]);
                    bool up = (lane & 16);
                    float dk = up ? dhi : dlo;
                    float ds = up ? dlo : dhi;
                    s16[i] = dk + __shfl_xor_sync(0xFFFFFFFFu, ds, 16);
                }
                float s8[8];
#pragma unroll
                for (int i = 0; i < 8; ++i) {
                    bool up = (lane & 8);
                    float k = up ? s16[8 + i] : s16[i];
                    float sn = up ? s16[i] : s16[8 + i];
                    s8[i] = k + __shfl_xor_sync(0xFFFFFFFFu, sn, 8);
                }
                float s4[4];
#pragma unroll
                for (int i = 0; i < 4; ++i) {
                    bool up = (lane & 4);
                    float k = up ? s8[4 + i] : s8[i];
                    float sn = up ? s8[i] : s8[4 + i];
                    s4[i] = k + __shfl_xor_sync(0xFFFFFFFFu, sn, 4);
                }
                float s2[2];
#pragma unroll
                for (int i = 0; i < 2; ++i) {
                    bool up = (lane & 2);
                    float k = up ? s4[2 + i] : s4[i];
                    float sn = up ? s4[i] : s4[2 + i];
                    s2[i] = k + __shfl_xor_sync(0xFFFFFFFFu, sn, 2);
                }
                {
                    bool up = (lane & 1);
                    float k = up ? s2[1] : s2[0];
                    float sn = up ? s2[0] : s2[1];
                    float s1 = k + __shfl_xor_sync(0xFFFFFFFFu, sn, 1);
                    pst[slot_s] = s1;
                    st_dsmem_f32(pst_addr + slot_s * 4u, peer, s1);
                }
                float q16[16];
#pragma unroll
                for (int i = 0; i < 16; ++i) {
                    float dlo = __uint_as_float(d[i]);
                    float dhi = __uint_as_float(d[16 + i]);
                    bool up = (lane & 16);
                    float dk = up ? dhi : dlo;
                    float ds = up ? dlo : dhi;
                    float rv = __shfl_xor_sync(0xFFFFFFFFu, ds, 16);
                    q16[i] = fmaf(dk, dk, rv * rv);
                }
                float q8[8];
#pragma unroll
                for (int i = 0; i < 8; ++i) {
                    bool up = (lane & 8);
                    float k = up ? q16[8 + i] : q16[i];
                    float sn = up ? q16[i] : q16[8 + i];
                    q8[i] = k + __shfl_xor_sync(0xFFFFFFFFu, sn, 8);
                }
                float q4[4];
#pragma unroll
                for (int i = 0; i < 4; ++i) {
                    bool up = (lane & 4);
                    float k = up ? q8[4 + i] : q8[i];
                    float sn = up ? q8[i] : q8[4 + i];
                    q4[i] = k + __shfl_xor_sync(0xFFFFFFFFu, sn, 4);
                }
                float q2[2];
#pragma unroll
                for (int i = 0; i < 2; ++i) {
                    bool up = (lane & 2);
                    float k = up ? q4[2 + i] : q4[i];
                    float sn = up ? q4[i] : q4[2 + i];
                    q2[i] = k + __shfl_xor_sync(0xFFFFFFFFu, sn, 2);
                }
                {
                    bool up = (lane & 1);
                    float k = up ? q2[1] : q2[0];
                    float sn = up ? q2[0] : q2[1];
                    float q1 = k + __shfl_xor_sync(0xFFFFFFFFu, sn, 1);
                    pst[slot_q] = q1;
                    st_dsmem_f32(pst_addr + slot_q * 4u, peer, q1);
                }
            }
            // all pushes (local + remote) visible cluster-wide
            CLUSTER_SYNC();

            if (tid < 128) {
                float ss = 0.f, qq = 0.f;
#pragma unroll
                for (int k = 0; k < 8; ++k) {
                    ss += pst[k * 128 + tid];
                    qq += pst[1024 + k * 128 + tid];
                }
                float mean = ss * (1.0f / 256.0f);
                float var = qq * (1.0f / 256.0f) - mean * mean;
                float inv = rsqrtf(var + 1e-5f);
                float gm = __ldg((layer ? G2 : G1) + tid);
                float bt = __ldg((layer ? B2 : B1) + tid);
                float scl = gm * inv;
                scv[tid] = scl;
                shv[tid] = bt - mean * scl;   // linear bias cancels in BN
            }
            __syncthreads();

            // normalize + ReLU, split to bf16 hi/lo, store next A (own half)
            {
#pragma unroll
                for (int c8 = 0; c8 < 4; ++c8) {
                    int j0 = jbase + c8 * 8;
                    float f[8];
#pragma unroll
                    for (int i = 0; i < 8; ++i) {
                        f[i] = fmaxf(fmaf(__uint_as_float(d[c8 * 8 + i]), scv[j0 + i], shv[j0 + i]), 0.f);
                    }
                    uint4 H, L;
                    split8f(f, H, L);
                    uint32_t off = swb(lrow, j0);
                    *(uint4*)(sm + OFF_AHI + off) = H;
                    *(uint4*)(sm + OFF_ALO + off) = L;
                }
            }
            FENCE_PROXY();
            // next iteration's CLUSTER_SYNC orders A'/W for the next MMA
        }
    }

    // ---- layer-3 epilogue: +b3, gate, write ----
    const int grow = (int)rank * 128 + lrow;
    const int q0 = jbase >> 2;
    if (is_c) {
#pragma unroll
        for (int q = 0; q < 8; ++q) {
            float4 bb = __ldg((const float4*)B3 + q0 + q);
            float4 v;
            v.x = __uint_as_float(d[4 * q + 0]) + bb.x;
            v.y = __uint_as_float(d[4 * q + 1]) + bb.y;
            v.z = __uint_as_float(d[4 * q + 2]) + bb.z;
            v.w = __uint_as_float(d[4 * q + 3]) + bb.w;
            g_c_out[grow * 32 + q0 + q] = v;
        }
        __threadfence();
        CLUSTER_SYNC();   // both c-CTAs' writes done
        if (rank == 0 && tid == 0) atomicExch(&g_flag, 1);
    } else {
        if (tid == 0) {
            while (atomicAdd(&g_flag, 0) == 0) { }
            __threadfence();
        }
        __syncthreads();
        float* op = out + ((size_t)grow * 512 + slice) * 128 + jbase;
#pragma unroll
        for (int q = 0; q < 8; ++q) {
            float4 bb = __ldg((const float4*)B3 + q0 + q);
            float4 cv = __ldcg(&g_c_out[grow * 32 + q0 + q]);
            float4 v;
            v.x = (__uint_as_float(d[4 * q + 0]) + bb.x) * cv.x;
            v.y = (__uint_as_float(d[4 * q + 1]) + bb.y) * cv.y;
            v.z = (__uint_as_float(d[4 * q + 2]) + bb.z) * cv.z;
            v.w = (__uint_as_float(d[4 * q + 3]) + bb.w) * cv.w;
            ((float4*)op)[q] = v;
        }
    }

    CLUSTER_SYNC();
    if (tid == 0) MBARRIER_INVAL(smb + OFF_MBAR);
    __syncthreads();
    if (wid == 0) TCGEN05_DEALLOC_CG2(tmem, 128);

#else
    // ============== FFMA2 fallback (compile-only; sm_103a SASS always runs) ==============
    if (blockIdx.x & 1) return;
    float* smf = (float*)smc;
    float* sm_act = smf;
    float* sm_wt  = smf + SM_ACT_F;
    float* sm_sc  = sm_wt + SM_WT_F;
    float* sm_sh  = sm_sc + 128;
    float* sm_gm  = sm_sh + 128;
    float* sm_bt  = sm_gm + 128;
    const int m = tid & 15;
    const int g = tid >> 4;

    {
        const float* src = is_c ? c : (s + (size_t)slice * 128);
        const size_t rstride = is_c ? (size_t)128 : (size_t)512 * 128;
        for (int idx = tid; idx < 256 * 32; idx += THREADS) {
            int r = idx >> 5;
            int kc = (idx & 31) << 2;
            float4 v = *(const float4*)(src + (size_t)r * rstride + kc);
            *(float4*)(sm_act + r * AP + kc) = v;
        }
    }
    load_wt(sm_wt, W1, tid);
    if (tid < 128) { sm_gm[tid] = G1[tid]; sm_bt[tid] = B1[tid]; }
    __syncthreads();

    u64 acc[8][4];
    fb_gemm(acc, sm_act, sm_wt, m, g);
    fb_bn_relu(acc, sm_act, sm_wt, sm_sc, sm_sh, sm_gm, sm_bt, m, g, tid);
    load_wt(sm_wt, W2, tid);
    if (tid < 128) { sm_gm[tid] = G2[tid]; sm_bt[tid] = B2[tid]; }
    __syncthreads();

    fb_gemm(acc, sm_act, sm_wt, m, g);
    fb_bn_relu(acc, sm_act, sm_wt, sm_sc, sm_sh, sm_gm, sm_bt, m, g, tid);
    load_wt(sm_wt, W3, tid);
    if (tid < 128) sm_bt[tid] = B3[tid];
    __syncthreads();

    fb_gemm(acc, sm_act, sm_wt, m, g);

    float* gco = (float*)g_c_out;
    if (is_c) {
#pragma unroll
        for (int p = 0; p < 4; ++p) {
            int j0 = 2 * m + 32 * p;
            float bb0 = sm_bt[j0], bb1 = sm_bt[j0 + 1];
#pragma unroll
            for (int i = 0; i < 8; ++i) {
                float lo, hi;
                unpack2(acc[i][p], lo, hi);
                float2 v; v.x = lo + bb0; v.y = hi + bb1;
                *(float2*)&gco[(g * 8 + i) * 128 + j0] = v;
            }
        }
        __threadfence();
        __syncthreads();
        if (tid == 0) atomicExch(&g_flag, 1);
    } else {
        if (tid == 0) {
            while (atomicAdd(&g_flag, 0) == 0) { }
            __threadfence();
        }
        __syncthreads();
#pragma unroll
        for (int p = 0; p < 4; ++p) {
            int j0 = 2 * m + 32 * p;
            float bb0 = sm_bt[j0], bb1 = sm_bt[j0 + 1];
#pragma unroll
            for (int i = 0; i < 8; ++i) {
                int r = g * 8 + i;
                float lo, hi;
                unpack2(acc[i][p], lo, hi);
                float2 cv = __ldcg((const float2*)&gco[r * 128 + j0]);
                float2 v;
                v.x = (lo + bb0) * cv.x;
                v.y = (hi + bb1) * cv.y;
                *(float2*)(out + ((size_t)r * 512 + slice) * 128 + j0) = v;
            }
        }
    }
#endif
}

// ---- Fused max-pool: blocks 0..1023 = partial max; blocks 1024..1055 spin
//      on g_done then finalize 256 outputs each. All 1056 CTAs co-resident
//      (occ 8/SM, 148 SMs -> 1184 slots) so the spin cannot deadlock. ----
__global__ void __launch_bounds__(256, 8)
maxpool_fused(const float* __restrict__ so, float* __restrict__ agg) {
    if (blockIdx.x < 1024) {
        __shared__ float4 red[8][32];
        int b = blockIdx.x >> 2;
        int seg = blockIdx.x & 3;
        int c4 = threadIdx.x & 31;
        int sub = threadIdx.x >> 5;
        const float4* p = (const float4*)(so + ((size_t)b * 512 + seg * 128 + sub * 16) * 128) + c4;
        float4 mx = make_float4(-3.4e38f, -3.4e38f, -3.4e38f, -3.4e38f);
#pragma unroll 16
        for (int i = 0; i < 16; ++i) {
            float4 v = p[(size_t)i * 32];
            mx.x = fmaxf(mx.x, v.x); mx.y = fmaxf(mx.y, v.y);
            mx.z = fmaxf(mx.z, v.z); mx.w = fmaxf(mx.w, v.w);
        }
        red[sub][c4] = mx;
        __syncthreads();
        if (threadIdx.x < 32) {
            float4 r = red[0][c4];
#pragma unroll
            for (int ss = 1; ss < 8; ++ss) {
                float4 v = red[ss][c4];
                r.x = fmaxf(r.x, v.x); r.y = fmaxf(r.y, v.y);
                r.z = fmaxf(r.z, v.z); r.w = fmaxf(r.w, v.w);
            }
            g_part[(size_t)blockIdx.x * 32 + c4] = r;
        }
        __syncthreads();
        if (threadIdx.x == 0) {
            __threadfence();
            atomicAdd(&g_done, 1);
        }
    } else {
        // finalizer: wait for all 1024 partials
        if (threadIdx.x == 0) {
            while (atomicAdd(&g_done, 0) < 1024) { __nanosleep(128); }
        }
        __syncthreads();
        __threadfence();
        int idx = (int)(blockIdx.x - 1024) * 256 + threadIdx.x;  // 0..8191
        int b = idx >> 5;
        int c4 = idx & 31;
        float4 r = g_part[(size_t)(b * 4) * 32 + c4];
#pragma unroll
        for (int seg = 1; seg < 4; ++seg) {
            float4 v = g_part[(size_t)(b * 4 + seg) * 32 + c4];
            r.x = fmaxf(r.x, v.x); r.y = fmaxf(r.y, v.y);
            r.z = fmaxf(r.z, v.z); r.w = fmaxf(r.w, v.w);
        }
        ((float4*)agg)[idx] = r;
        // last finalizer resets counters/flags for graph replay
        __syncthreads();
        if (threadIdx.x == 0) {
            int f = atomicAdd(&g_fin, 1);
            if (f == 31) {
                g_done = 0;
                g_fin = 0;
                g_flag = 0;
            }
        }
    }
}

extern "C" void kernel_launch(void* const* d_in, const int* in_sizes, int n_in,
                              void* d_out, int out_size) {
    const float* s    = (const float*)d_in[0];
    const float* c    = (const float*)d_in[1];
    const float* sw1  = (const float*)d_in[2];
    const float* sg1  = (const float*)d_in[4];
    const float* sbe1 = (const float*)d_in[5];
    const float* sw2  = (const float*)d_in[6];
    const float* sg2  = (const float*)d_in[8];
    const float* sbe2 = (const float*)d_in[9];
    const float* sw3  = (const float*)d_in[10];
    const float* sb3  = (const float*)d_in[11];
    const float* cw1  = (const float*)d_in[12];
    const float* cg1  = (const float*)d_in[14];
    const float* cbe1 = (const float*)d_in[15];
    const float* cw2  = (const float*)d_in[16];
    const float* cg2  = (const float*)d_in[18];
    const float* cbe2 = (const float*)d_in[19];
    const float* cw3  = (const float*)d_in[20];
    const float* cb3  = (const float*)d_in[21];
    float* out = (float*)d_out;

    cudaFuncSetAttribute(mlp_kernel, cudaFuncAttributeMaxDynamicSharedMemorySize, SM_TC_BYTES);

    // 513 clusters x 2 CTAs: cluster 0 = c-path, clusters 1..512 = slices
    mlp_kernel<<<1026, THREADS, SM_TC_BYTES>>>(s, c,
                                               sw1, sg1, sbe1, sw2, sg2, sbe2, sw3, sb3,
                                               cw1, cg1, cbe1, cw2, cg2, cbe2, cw3, cb3,
                                               out);

    float* agg = out + ((size_t)out_size - 256 * 128);
    maxpool_fused<<<1056, 256>>>(out, agg);
}